// round 12
// baseline (speedup 1.0000x reference)
#include <cuda_runtime.h>
#include <cuda_bf16.h>
#include <stdint.h>

// Problem constants
#define NN   50000
#define EE   800000
#define GG   512
#define DIN  128
#define HH   64
#define ZS   192              // L*H, row stride of z_cat and pool
#define BN_EPS 1e-5f

// scratch layout inside zc cols [128,192) viewed as int32 (free until bn_apply(L1))
#define SCR_A 0          // counts -> cursor, NN ints
#define SCR_B 51200      // offsets, NN+1 ints
#define SCR_L 102656     // dst-sorted src list, EE ints (ends 902656 < 3.2M)

// ---------------- tiny device globals (~2 KB; device-code access only) ----------------
__device__ __align__(16) float g_stats[384];   // per layer: [0:64) sum, [64:128) sumsq
__device__ int g_is64;

// ---------------- helpers ----------------
__device__ __forceinline__ void red4(float* p, float4 v) {
    atomicAdd(reinterpret_cast<float4*>(p), v);
}

__device__ __forceinline__ long long ldidx(const void* p, long long i, int is64) {
    if (is64) return ((const long long*)p)[i];
    return (long long)((const int*)p)[i];
}

// strided scratch accessor: int slot i -> zc[(i/64)*192 + 128 + i%64]
__device__ __forceinline__ int* scr(float* zc, int i) {
    return reinterpret_cast<int*>(zc) + (long long)(i >> 6) * ZS + 128 + (i & 63);
}

// ---------------- setup: zero pool + stats + counts, detect index dtype ----------------
__global__ void setup_kernel(float* zc, float* pool, const long long* ei) {
    int gt = blockIdx.x * 256 + threadIdx.x;
    for (int i = gt; i < GG * ZS; i += gridDim.x * 256) pool[i] = 0.0f;
    for (int i = gt; i < NN; i += gridDim.x * 256) *scr(zc, SCR_A + i) = 0;
    if (blockIdx.x == 0) {
        if (threadIdx.x < 128) {
            g_stats[threadIdx.x] = 0.0f;
            g_stats[threadIdx.x + 128] = 0.0f;
            g_stats[threadIdx.x + 256] = 0.0f;
        }
        if (threadIdx.x == 0) {
            int ok = 1;
            for (int i = 0; i < 16; i++) {
                long long v = ei[i];
                if (v < 0 || v >= NN) ok = 0;
            }
            g_is64 = ok;
        }
    }
}

// ---------------- counting sort of edges by dst ----------------
__global__ void hist_kernel(float* zc, const void* __restrict__ ei) {
    int e = blockIdx.x * 256 + threadIdx.x;
    if (e >= EE) return;
    int d = (int)ldidx(ei, (long long)EE + e, g_is64);
    atomicAdd(scr(zc, SCR_A + d), 1);
}

// Single-block exclusive scan over NN counts -> offsets (SCR_B) + cursor (SCR_A).
#define SCAN_CH 49   // 1024 * 49 >= NN
__global__ void scan_kernel(float* zc) {
    __shared__ int sh[1024];
    int t = threadIdx.x;
    int base = t * SCAN_CH;
    int sum = 0;
    for (int j = 0; j < SCAN_CH; j++) {
        int i = base + j;
        if (i < NN) sum += *scr(zc, SCR_A + i);
    }
    sh[t] = sum;
    __syncthreads();
    for (int s = 1; s < 1024; s <<= 1) {
        int a = (t >= s) ? sh[t - s] : 0;
        __syncthreads();
        sh[t] += a;
        __syncthreads();
    }
    int run = sh[t] - sum;   // exclusive base for this chunk
    for (int j = 0; j < SCAN_CH; j++) {
        int i = base + j;
        if (i < NN) {
            int c = *scr(zc, SCR_A + i);
            *scr(zc, SCR_B + i) = run;
            *scr(zc, SCR_A + i) = run;   // cursor init
            run += c;
        }
    }
    if (t == 0) *scr(zc, SCR_B + NN) = EE;
}

__global__ void place_kernel(float* zc, const void* __restrict__ ei) {
    int e = blockIdx.x * 256 + threadIdx.x;
    if (e >= EE) return;
    int is64 = g_is64;
    int s = (int)ldidx(ei, e, is64);
    int d = (int)ldidx(ei, (long long)EE + e, is64);
    int pos = atomicAdd(scr(zc, SCR_A + d), 1);
    *scr(zc, SCR_L + pos) = s;
}

// ---------------- gather: one warp per dst row; agg[n] = src[n] + sum src[list] ----------
__global__ void __launch_bounds__(256) gather_kernel(float* zc, int src_col, int agg_col) {
    int n = (blockIdx.x * 256 + threadIdx.x) >> 5;
    int lane = threadIdx.x & 31;
    if (n >= NN) return;
    const float* self = zc + (long long)n * ZS + src_col;
    float a0 = self[lane], a1 = self[lane + 32];
    int start = *scr(zc, SCR_B + n);
    int end   = *scr(zc, SCR_B + n + 1);
    float p0 = 0, p1 = 0, q0 = 0, q1 = 0, u0 = 0, u1 = 0, t0 = 0, t1 = 0;
    int e = start;
    for (; e + 3 < end; e += 4) {
        int s0 = *scr(zc, SCR_L + e);
        int s1 = *scr(zc, SCR_L + e + 1);
        int s2 = *scr(zc, SCR_L + e + 2);
        int s3 = *scr(zc, SCR_L + e + 3);
        const float* r0 = zc + (long long)s0 * ZS + src_col;
        const float* r1 = zc + (long long)s1 * ZS + src_col;
        const float* r2 = zc + (long long)s2 * ZS + src_col;
        const float* r3 = zc + (long long)s3 * ZS + src_col;
        p0 += r0[lane]; p1 += r0[lane + 32];
        q0 += r1[lane]; q1 += r1[lane + 32];
        u0 += r2[lane]; u1 += r2[lane + 32];
        t0 += r3[lane]; t1 += r3[lane + 32];
    }
    for (; e < end; e++) {
        int s0 = *scr(zc, SCR_L + e);
        const float* r0 = zc + (long long)s0 * ZS + src_col;
        p0 += r0[lane]; p1 += r0[lane + 32];
    }
    a0 += (p0 + q0) + (u0 + t0);
    a1 += (p1 + q1) + (u1 + t1);
    float* out = zc + (long long)n * ZS + agg_col;
    out[lane] = a0;
    out[lane + 32] = a1;
}

// ======================= GEMM building blocks =======================
// Block 128 threads, 64 nodes. Thread (ng=tid>>3, fg=tid&7) owns 4 nodes x 8 features.

__device__ __forceinline__ void stage_w(float* Ws, const float* __restrict__ W, int tid) {
    for (int i = tid; i < 1024; i += 128)
        reinterpret_cast<float4*>(Ws)[i] = reinterpret_cast<const float4*>(W)[i];
}

__device__ __forceinline__ void stage_x(float* Xs, const float* __restrict__ gx,
                                        int zstride, int node0, int tid) {
    int row = tid >> 1, part = tid & 1;
    int gn = node0 + row; if (gn >= NN) gn = NN - 1;
    const float4* src = reinterpret_cast<const float4*>(gx + (long long)gn * zstride);
    float4* dst = reinterpret_cast<float4*>(Xs + row * 68);
#pragma unroll
    for (int q = 0; q < 8; q++) dst[part * 8 + q] = src[part * 8 + q];
}

// acc += Xs(64x64) @ Ws(64x64); float4 X reads (k-vectorized)
__device__ __forceinline__ void gemm_core(const float* Xs, const float* Ws,
                                          int ng, int fg, float* acc) {
#pragma unroll
    for (int k4 = 0; k4 < 16; k4++) {
        float4 xv0 = *reinterpret_cast<const float4*>(Xs + (ng * 4 + 0) * 68 + k4 * 4);
        float4 xv1 = *reinterpret_cast<const float4*>(Xs + (ng * 4 + 1) * 68 + k4 * 4);
        float4 xv2 = *reinterpret_cast<const float4*>(Xs + (ng * 4 + 2) * 68 + k4 * 4);
        float4 xv3 = *reinterpret_cast<const float4*>(Xs + (ng * 4 + 3) * 68 + k4 * 4);
#pragma unroll
        for (int kk = 0; kk < 4; kk++) {
            const float4* wr = reinterpret_cast<const float4*>(Ws + (k4 * 4 + kk) * 64 + fg * 8);
            float4 wa = wr[0], wb = wr[1];
            float v0 = (kk == 0) ? xv0.x : (kk == 1) ? xv0.y : (kk == 2) ? xv0.z : xv0.w;
            float v1 = (kk == 0) ? xv1.x : (kk == 1) ? xv1.y : (kk == 2) ? xv1.z : xv1.w;
            float v2 = (kk == 0) ? xv2.x : (kk == 1) ? xv2.y : (kk == 2) ? xv2.z : xv2.w;
            float v3 = (kk == 0) ? xv3.x : (kk == 1) ? xv3.y : (kk == 2) ? xv3.z : xv3.w;
            acc[0]  += v0 * wa.x; acc[1]  += v0 * wa.y; acc[2]  += v0 * wa.z; acc[3]  += v0 * wa.w;
            acc[4]  += v0 * wb.x; acc[5]  += v0 * wb.y; acc[6]  += v0 * wb.z; acc[7]  += v0 * wb.w;
            acc[8]  += v1 * wa.x; acc[9]  += v1 * wa.y; acc[10] += v1 * wa.z; acc[11] += v1 * wa.w;
            acc[12] += v1 * wb.x; acc[13] += v1 * wb.y; acc[14] += v1 * wb.z; acc[15] += v1 * wb.w;
            acc[16] += v2 * wa.x; acc[17] += v2 * wa.y; acc[18] += v2 * wa.z; acc[19] += v2 * wa.w;
            acc[20] += v2 * wb.x; acc[21] += v2 * wb.y; acc[22] += v2 * wb.z; acc[23] += v2 * wb.w;
            acc[24] += v3 * wa.x; acc[25] += v3 * wa.y; acc[26] += v3 * wa.z; acc[27] += v3 * wa.w;
            acc[28] += v3 * wb.x; acc[29] += v3 * wb.y; acc[30] += v3 * wb.z; acc[31] += v3 * wb.w;
        }
    }
}

// per-block BN-stat partials into g_stats[stats_off..]; S >= 16*130 floats scratch.
__device__ __forceinline__ void stats_epi(float* S, const float* o, int stats_off,
                                          int ng, int fg, int node0, int tid) {
    float s[8], q[8];
#pragma unroll
    for (int j = 0; j < 8; j++) { s[j] = 0.0f; q[j] = 0.0f; }
#pragma unroll
    for (int i = 0; i < 4; i++) {
        if (node0 + ng * 4 + i < NN) {
#pragma unroll
            for (int j = 0; j < 8; j++) { float v = o[i*8+j]; s[j] += v; q[j] += v * v; }
        }
    }
#pragma unroll
    for (int j = 0; j < 8; j++) {
        S[ng * 130 + fg * 8 + j] = s[j];
        S[ng * 130 + 65 + fg * 8 + j] = q[j];
    }
    __syncthreads();
    int f = tid & 63, which = tid >> 6;
    float a = 0.0f;
#pragma unroll
    for (int g = 0; g < 16; g++) a += S[g * 130 + which * 65 + f];
    atomicAdd(&g_stats[stats_off + which * 64 + f], a);
}

// ---------------- L0 projection: y0 = x @ W1 (128->64) -> zc cols [64,128) ----------------
__global__ void __launch_bounds__(128) gemm1_kernel(
    const float* __restrict__ x, const float* __restrict__ W1, float* zc)
{
    __shared__ float Ws[4096];
    __shared__ float Xs[64 * 68];
    const int tid = threadIdx.x, fg = tid & 7, ng = tid >> 3;
    const int node0 = blockIdx.x * 64;

    float acc[32];
#pragma unroll
    for (int q = 0; q < 32; q++) acc[q] = 0.0f;

    for (int kc = 0; kc < 2; kc++) {
        __syncthreads();
        stage_w(Ws, W1 + kc * 64 * 64, tid);
        stage_x(Xs, x + kc * 64, DIN, node0, tid);
        __syncthreads();
        gemm_core(Xs, Ws, ng, fg, acc);
    }

#pragma unroll
    for (int i = 0; i < 4; i++) {
        int node = node0 + ng * 4 + i;
        if (node < NN) {
            float* row = zc + (long long)node * ZS + 64;
            *reinterpret_cast<float4*>(row + fg * 8) =
                make_float4(acc[i*8+0], acc[i*8+1], acc[i*8+2], acc[i*8+3]);
            *reinterpret_cast<float4*>(row + fg * 8 + 4) =
                make_float4(acc[i*8+4], acc[i*8+5], acc[i*8+6], acc[i*8+7]);
        }
    }
}

// ---------------- L0 MLP tail: h = relu( relu(agg+b1) @ W2 + b2 ), in place + stats ------
__global__ void __launch_bounds__(128) mlp0_kernel(
    float* zc, int col, int stats_off,
    const float* __restrict__ W2, const float* __restrict__ b1,
    const float* __restrict__ b2)
{
    __shared__ float Ws[4096];
    __shared__ float Xs[64 * 68];
    const int tid = threadIdx.x, fg = tid & 7, ng = tid >> 3;
    const int node0 = blockIdx.x * 64;

    stage_w(Ws, W2, tid);
    {   // Xs = relu(agg + b1)
        int row = tid >> 1, part = tid & 1;
        int gn = node0 + row; if (gn >= NN) gn = NN - 1;
        const float4* src = reinterpret_cast<const float4*>(zc + (long long)gn * ZS + col);
        float4* dst = reinterpret_cast<float4*>(Xs + row * 68);
#pragma unroll
        for (int q = 0; q < 8; q++) {
            int c4 = part * 8 + q;
            float4 a = src[c4];
            float4 bb = reinterpret_cast<const float4*>(b1)[c4];
            dst[c4] = make_float4(fmaxf(a.x + bb.x, 0.0f), fmaxf(a.y + bb.y, 0.0f),
                                  fmaxf(a.z + bb.z, 0.0f), fmaxf(a.w + bb.w, 0.0f));
        }
    }
    __syncthreads();

    float acc[32];
    {
        float4 ba = reinterpret_cast<const float4*>(b2)[fg * 2];
        float4 bb = reinterpret_cast<const float4*>(b2)[fg * 2 + 1];
#pragma unroll
        for (int i = 0; i < 4; i++) {
            acc[i*8+0] = ba.x; acc[i*8+1] = ba.y; acc[i*8+2] = ba.z; acc[i*8+3] = ba.w;
            acc[i*8+4] = bb.x; acc[i*8+5] = bb.y; acc[i*8+6] = bb.z; acc[i*8+7] = bb.w;
        }
    }
    gemm_core(Xs, Ws, ng, fg, acc);
#pragma unroll
    for (int q = 0; q < 32; q++) acc[q] = fmaxf(acc[q], 0.0f);

#pragma unroll
    for (int i = 0; i < 4; i++) {
        int node = node0 + ng * 4 + i;
        if (node < NN) {
            float* row = zc + (long long)node * ZS + col;
            *reinterpret_cast<float4*>(row + fg * 8) =
                make_float4(acc[i*8+0], acc[i*8+1], acc[i*8+2], acc[i*8+3]);
            *reinterpret_cast<float4*>(row + fg * 8 + 4) =
                make_float4(acc[i*8+4], acc[i*8+5], acc[i*8+6], acc[i*8+7]);
        }
    }
    __syncthreads();
    stats_epi(Ws, acc, stats_off, ng, fg, node0, tid);
}

// ---------------- L1/L2 MLP: h = relu( relu(agg@W1+b1) @ W2 + b2 ) + stats ----------------
__global__ void __launch_bounds__(128) mlp2_kernel(
    float* zc, int in_col, int out_col, int stats_off,
    const float* __restrict__ W1, const float* __restrict__ b1,
    const float* __restrict__ W2, const float* __restrict__ b2)
{
    __shared__ float Ws[4096];
    __shared__ float Xs[64 * 68];
    const int tid = threadIdx.x, fg = tid & 7, ng = tid >> 3;
    const int node0 = blockIdx.x * 64;

    stage_w(Ws, W1, tid);
    stage_x(Xs, zc + in_col, ZS, node0, tid);
    __syncthreads();

    float acc[32];
#pragma unroll
    for (int q = 0; q < 32; q++) acc[q] = 0.0f;
    gemm_core(Xs, Ws, ng, fg, acc);
    __syncthreads();

    {
        float4 ba = reinterpret_cast<const float4*>(b1)[fg * 2];
        float4 bb = reinterpret_cast<const float4*>(b1)[fg * 2 + 1];
#pragma unroll
        for (int i = 0; i < 4; i++) {
            float* hr = Xs + (ng * 4 + i) * 68 + fg * 8;
            *reinterpret_cast<float4*>(hr) =
                make_float4(fmaxf(acc[i*8+0]+ba.x,0.f), fmaxf(acc[i*8+1]+ba.y,0.f),
                            fmaxf(acc[i*8+2]+ba.z,0.f), fmaxf(acc[i*8+3]+ba.w,0.f));
            *reinterpret_cast<float4*>(hr + 4) =
                make_float4(fmaxf(acc[i*8+4]+bb.x,0.f), fmaxf(acc[i*8+5]+bb.y,0.f),
                            fmaxf(acc[i*8+6]+bb.z,0.f), fmaxf(acc[i*8+7]+bb.w,0.f));
        }
    }
    stage_w(Ws, W2, tid);
    __syncthreads();

    {
        float4 ba = reinterpret_cast<const float4*>(b2)[fg * 2];
        float4 bb = reinterpret_cast<const float4*>(b2)[fg * 2 + 1];
#pragma unroll
        for (int i = 0; i < 4; i++) {
            acc[i*8+0] = ba.x; acc[i*8+1] = ba.y; acc[i*8+2] = ba.z; acc[i*8+3] = ba.w;
            acc[i*8+4] = bb.x; acc[i*8+5] = bb.y; acc[i*8+6] = bb.z; acc[i*8+7] = bb.w;
        }
    }
    gemm_core(Xs, Ws, ng, fg, acc);
#pragma unroll
    for (int q = 0; q < 32; q++) acc[q] = fmaxf(acc[q], 0.0f);

#pragma unroll
    for (int i = 0; i < 4; i++) {
        int node = node0 + ng * 4 + i;
        if (node < NN) {
            float* row = zc + (long long)node * ZS + out_col;
            *reinterpret_cast<float4*>(row + fg * 8) =
                make_float4(acc[i*8+0], acc[i*8+1], acc[i*8+2], acc[i*8+3]);
            *reinterpret_cast<float4*>(row + fg * 8 + 4) =
                make_float4(acc[i*8+4], acc[i*8+5], acc[i*8+6], acc[i*8+7]);
        }
    }
    __syncthreads();
    stats_epi(Ws, acc, stats_off, ng, fg, node0, tid);
}

// ---------------- L2 RED scatter (agg col init'd with z1 copy by bn_apply) ----------------
__global__ void scatter_kernel(float* zc, int src_col, int agg_col,
                               const void* __restrict__ ei) {
    int gtid = blockIdx.x * 256 + threadIdx.x;
    int e = gtid >> 3;
    int c = gtid & 7;
    if (e >= EE) return;
    int is64 = g_is64;
    long long s = ldidx(ei, e, is64);
    long long d = ldidx(ei, (long long)EE + e, is64);
    const float4* sp = reinterpret_cast<const float4*>(zc + s * ZS + src_col);
    float4 v0 = sp[c];
    float4 v1 = sp[c + 8];
    float* dp = zc + d * ZS + agg_col;
    red4(dp + c * 4, v0);
    red4(dp + 32 + c * 4, v1);
}

// ---------------- BN apply: finalize (per block, from stats) + normalize + pool + copy ----
__global__ void bn_apply_kernel(float* zc, int col_off, int copy_off, int stats_off,
                                const void* __restrict__ batch,
                                float* __restrict__ pool,
                                const float* __restrict__ gam,
                                const float* __restrict__ bet)
{
    __shared__ __align__(16) float sc_s[64], sh_s[64];
    int t = threadIdx.x;
    if (t < 64) {
        float mean = g_stats[stats_off + t] * (1.0f / NN);
        float var = g_stats[stats_off + 64 + t] * (1.0f / NN) - mean * mean;
        var = fmaxf(var, 0.0f);
        float s = gam[t] * rsqrtf(var + BN_EPS);
        sc_s[t] = s;
        sh_s[t] = bet[t] - mean * s;
    }
    __syncthreads();

    int gt = blockIdx.x * 256 + t;
    int n = gt >> 4;
    int c = gt & 15;
    if (n >= NN) return;
    int is64 = g_is64;
    float* row = zc + (long long)n * ZS;
    float4 h4 = *reinterpret_cast<float4*>(row + col_off + c * 4);
    float4 sc = *reinterpret_cast<const float4*>(sc_s + c * 4);
    float4 sh = *reinterpret_cast<const float4*>(sh_s + c * 4);
    float4 z;
    z.x = h4.x * sc.x + sh.x;
    z.y = h4.y * sc.y + sh.y;
    z.z = h4.z * sc.z + sh.z;
    z.w = h4.w * sc.w + sh.w;
    *reinterpret_cast<float4*>(row + col_off + c * 4) = z;
    if (copy_off >= 0)
        *reinterpret_cast<float4*>(row + copy_off + c * 4) = z;
    long long b = ldidx(batch, n, is64);
    red4(pool + b * ZS + col_off + c * 4, z);
}

// ---------------- launch ----------------
extern "C" void kernel_launch(void* const* d_in, const int* in_sizes, int n_in,
                              void* d_out, int out_size)
{
    const float* x     = (const float*)d_in[0];
    const void*  ei    = d_in[1];
    const void*  batch = d_in[2];
    const float* W1_0  = (const float*)d_in[3];
    const float* b1_0  = (const float*)d_in[4];
    const float* W2_0  = (const float*)d_in[5];
    const float* b2_0  = (const float*)d_in[6];
    const float* bn_g0 = (const float*)d_in[7];
    const float* bn_b0 = (const float*)d_in[8];
    const float* W1_r  = (const float*)d_in[9];
    const float* b1_r  = (const float*)d_in[10];
    const float* W2_r  = (const float*)d_in[11];
    const float* b2_r  = (const float*)d_in[12];
    const float* bn_gr = (const float*)d_in[13];
    const float* bn_br = (const float*)d_in[14];

    float* zc   = (float*)d_out;
    float* pool = zc + (long long)NN * ZS;

    const int gemm_grid = (NN + 63) / 64;            // 782
    const int edge_grid = (EE + 255) / 256;          // 3125
    const int gath_grid = (NN * 32 + 255) / 256;     // 6250
    const int scat_grid = (EE * 8) / 256;            // 25000
    const int bn_grid   = (NN * 16 + 255) / 256;     // 3125

    // setup + dst-sort of edges (list lives in zc cols 128.. until bn_apply(L1))
    setup_kernel<<<256, 256>>>(zc, pool, (const long long*)ei);
    hist_kernel<<<edge_grid, 256>>>(zc, ei);
    scan_kernel<<<1, 1024>>>(zc);
    place_kernel<<<edge_grid, 256>>>(zc, ei);

    // ---- layer 0: y0 = x@W1 -> col 64; gather y0 -> agg @ col 0; MLP in place @ 0 ----
    gemm1_kernel<<<gemm_grid, 128>>>(x, W1_0, zc);
    gather_kernel<<<gath_grid, 256>>>(zc, 64, 0);
    mlp0_kernel<<<gemm_grid, 128>>>(zc, 0, 0, W2_0, b1_0, b2_0);
    bn_apply_kernel<<<bn_grid, 256>>>(zc, 0, -1, 0, batch, pool, bn_g0, bn_b0);

    // ---- layer 1: gather z0 (col 0) -> agg @ col 64; MLP in place @ 64 ----
    gather_kernel<<<gath_grid, 256>>>(zc, 0, 64);
    mlp2_kernel<<<gemm_grid, 128>>>(zc, 64, 64, 128, W1_r, b1_r, W2_r, b2_r);
    bn_apply_kernel<<<bn_grid, 256>>>(zc, 64, 128, 128, batch, pool, bn_gr, bn_br);  // copy z1->128

    // ---- layer 2: RED scatter (z1 @64 -> agg @128) + MLP in place @128 ----
    scatter_kernel<<<scat_grid, 256>>>(zc, 64, 128, ei);
    mlp2_kernel<<<gemm_grid, 128>>>(zc, 128, 128, 256,
                                    W1_r + (size_t)HH * HH, b1_r + HH,
                                    W2_r + (size_t)HH * HH, b2_r + HH);
    bn_apply_kernel<<<bn_grid, 256>>>(zc, 128, -1, 256, batch, pool, bn_gr + HH, bn_br + HH);

    (void)in_sizes; (void)n_in; (void)out_size;
}

// round 13
// speedup vs baseline: 1.2288x; 1.2288x over previous
#include <cuda_runtime.h>
#include <cuda_bf16.h>
#include <stdint.h>

// Problem constants
#define NN   50000
#define EE   800000
#define GG   512
#define DIN  128
#define HH   64
#define ZS   192              // L*H, row stride of z_cat and pool
#define BN_EPS 1e-5f

// scratch layout inside zc cols [128,192) viewed as int32 (free until bn_apply(L1))
#define SCR_A 0          // counts -> cursor, NN ints
#define SCR_B 51200      // offsets, NN+1 ints
#define SCR_P 102400     // scan partials, 196 ints
#define SCR_L 102656     // dst-sorted src list, EE ints (ends 902656 < 3.2M)
#define SCAN_NB 196      // ceil(NN/256)

// ---------------- tiny device globals (~2 KB; device-code access only) ----------------
__device__ __align__(16) float g_stats[384];   // per layer: [0:64) sum, [64:128) sumsq
__device__ int g_is64;

// ---------------- helpers ----------------
__device__ __forceinline__ void red4(float* p, float4 v) {
    atomicAdd(reinterpret_cast<float4*>(p), v);
}

__device__ __forceinline__ long long ldidx(const void* p, long long i, int is64) {
    if (is64) return ((const long long*)p)[i];
    return (long long)((const int*)p)[i];
}

// strided scratch accessor: int slot i -> zc[(i/64)*192 + 128 + i%64]
__device__ __forceinline__ int* scr(float* zc, int i) {
    return reinterpret_cast<int*>(zc) + (long long)(i >> 6) * ZS + 128 + (i & 63);
}

// ---------------- setup: zero pool + stats + counts, detect index dtype ----------------
__global__ void setup_kernel(float* zc, float* pool, const long long* ei) {
    int gt = blockIdx.x * 256 + threadIdx.x;
    for (int i = gt; i < GG * ZS; i += gridDim.x * 256) pool[i] = 0.0f;
    for (int i = gt; i < NN; i += gridDim.x * 256) *scr(zc, SCR_A + i) = 0;
    if (blockIdx.x == 0) {
        if (threadIdx.x < 128) {
            g_stats[threadIdx.x] = 0.0f;
            g_stats[threadIdx.x + 128] = 0.0f;
            g_stats[threadIdx.x + 256] = 0.0f;
        }
        if (threadIdx.x == 0) {
            int ok = 1;
            for (int i = 0; i < 16; i++) {
                long long v = ei[i];
                if (v < 0 || v >= NN) ok = 0;
            }
            g_is64 = ok;
        }
    }
}

// ---------------- counting sort of edges by dst (multi-block scan, R11 form) -------------
__global__ void hist_kernel(float* zc, const void* __restrict__ ei) {
    int e = blockIdx.x * 256 + threadIdx.x;
    if (e >= EE) return;
    int d = (int)ldidx(ei, (long long)EE + e, g_is64);
    atomicAdd(scr(zc, SCR_A + d), 1);
}

__device__ __forceinline__ int block_incl_scan(int* sh, int t, int v) {
    sh[t] = v;
    __syncthreads();
#pragma unroll
    for (int s = 1; s < 256; s <<= 1) {
        int add = (t >= s) ? sh[t - s] : 0;
        __syncthreads();
        sh[t] += add;
        __syncthreads();
    }
    return sh[t];
}

__global__ void scan_partials_kernel(float* zc) {
    __shared__ int sh[256];
    int t = threadIdx.x;
    int i = blockIdx.x * 256 + t;
    int c = (i < NN) ? *scr(zc, SCR_A + i) : 0;
    sh[t] = c;
    __syncthreads();
    for (int s = 128; s > 0; s >>= 1) {
        if (t < s) sh[t] += sh[t + s];
        __syncthreads();
    }
    if (t == 0) *scr(zc, SCR_P + blockIdx.x) = sh[0];
}

__global__ void scan_top_kernel(float* zc) {
    __shared__ int sh[256];
    int t = threadIdx.x;
    int v = (t < SCAN_NB) ? *scr(zc, SCR_P + t) : 0;
    int inc = block_incl_scan(sh, t, v);
    if (t < SCAN_NB) *scr(zc, SCR_P + t) = inc - v;   // exclusive
    if (t == 0) *scr(zc, SCR_B + NN) = EE;
}

__global__ void scan_apply_kernel(float* zc) {
    __shared__ int sh[256];
    int t = threadIdx.x;
    int i = blockIdx.x * 256 + t;
    int c = (i < NN) ? *scr(zc, SCR_A + i) : 0;
    int inc = block_incl_scan(sh, t, c);
    int base = *scr(zc, SCR_P + blockIdx.x);
    if (i < NN) {
        int off = base + inc - c;      // exclusive prefix
        *scr(zc, SCR_B + i) = off;     // offsets
        *scr(zc, SCR_A + i) = off;     // cursor init
    }
}

__global__ void place_kernel(float* zc, const void* __restrict__ ei) {
    int e = blockIdx.x * 256 + threadIdx.x;
    if (e >= EE) return;
    int is64 = g_is64;
    int s = (int)ldidx(ei, e, is64);
    int d = (int)ldidx(ei, (long long)EE + e, is64);
    int pos = atomicAdd(scr(zc, SCR_A + d), 1);
    *scr(zc, SCR_L + pos) = s;
}

// ---------------- gather: one warp per dst row; agg[n] = src[n] + sum src[list] ----------
__global__ void __launch_bounds__(256) gather_kernel(float* zc, int src_col, int agg_col) {
    int n = (blockIdx.x * 256 + threadIdx.x) >> 5;
    int lane = threadIdx.x & 31;
    if (n >= NN) return;
    const float* self = zc + (long long)n * ZS + src_col;
    float a0 = self[lane], a1 = self[lane + 32];
    int start = *scr(zc, SCR_B + n);
    int end   = *scr(zc, SCR_B + n + 1);
    float p0 = 0, p1 = 0, q0 = 0, q1 = 0, u0 = 0, u1 = 0, t0 = 0, t1 = 0;
    int e = start;
    for (; e + 3 < end; e += 4) {
        int s0 = *scr(zc, SCR_L + e);
        int s1 = *scr(zc, SCR_L + e + 1);
        int s2 = *scr(zc, SCR_L + e + 2);
        int s3 = *scr(zc, SCR_L + e + 3);
        const float* r0 = zc + (long long)s0 * ZS + src_col;
        const float* r1 = zc + (long long)s1 * ZS + src_col;
        const float* r2 = zc + (long long)s2 * ZS + src_col;
        const float* r3 = zc + (long long)s3 * ZS + src_col;
        p0 += r0[lane]; p1 += r0[lane + 32];
        q0 += r1[lane]; q1 += r1[lane + 32];
        u0 += r2[lane]; u1 += r2[lane + 32];
        t0 += r3[lane]; t1 += r3[lane + 32];
    }
    for (; e < end; e++) {
        int s0 = *scr(zc, SCR_L + e);
        const float* r0 = zc + (long long)s0 * ZS + src_col;
        p0 += r0[lane]; p1 += r0[lane + 32];
    }
    a0 += (p0 + q0) + (u0 + t0);
    a1 += (p1 + q1) + (u1 + t1);
    float* out = zc + (long long)n * ZS + agg_col;
    out[lane] = a0;
    out[lane + 32] = a1;
}

// ======================= GEMM building blocks =======================
// Block 128 threads, 64 nodes. Thread (ng=tid>>3, fg=tid&7) owns 4 nodes x 8 features.

__device__ __forceinline__ void stage_w(float* Ws, const float* __restrict__ W, int tid) {
    for (int i = tid; i < 1024; i += 128)
        reinterpret_cast<float4*>(Ws)[i] = reinterpret_cast<const float4*>(W)[i];
}

__device__ __forceinline__ void stage_x(float* Xs, const float* __restrict__ gx,
                                        int zstride, int node0, int tid) {
    int row = tid >> 1, part = tid & 1;
    int gn = node0 + row; if (gn >= NN) gn = NN - 1;
    const float4* src = reinterpret_cast<const float4*>(gx + (long long)gn * zstride);
    float4* dst = reinterpret_cast<float4*>(Xs + row * 68);
#pragma unroll
    for (int q = 0; q < 8; q++) dst[part * 8 + q] = src[part * 8 + q];
}

// acc += Xs(64x64) @ Ws(64x64); float4 X reads (k-vectorized)
__device__ __forceinline__ void gemm_core(const float* Xs, const float* Ws,
                                          int ng, int fg, float* acc) {
#pragma unroll
    for (int k4 = 0; k4 < 16; k4++) {
        float4 xv0 = *reinterpret_cast<const float4*>(Xs + (ng * 4 + 0) * 68 + k4 * 4);
        float4 xv1 = *reinterpret_cast<const float4*>(Xs + (ng * 4 + 1) * 68 + k4 * 4);
        float4 xv2 = *reinterpret_cast<const float4*>(Xs + (ng * 4 + 2) * 68 + k4 * 4);
        float4 xv3 = *reinterpret_cast<const float4*>(Xs + (ng * 4 + 3) * 68 + k4 * 4);
#pragma unroll
        for (int kk = 0; kk < 4; kk++) {
            const float4* wr = reinterpret_cast<const float4*>(Ws + (k4 * 4 + kk) * 64 + fg * 8);
            float4 wa = wr[0], wb = wr[1];
            float v0 = (kk == 0) ? xv0.x : (kk == 1) ? xv0.y : (kk == 2) ? xv0.z : xv0.w;
            float v1 = (kk == 0) ? xv1.x : (kk == 1) ? xv1.y : (kk == 2) ? xv1.z : xv1.w;
            float v2 = (kk == 0) ? xv2.x : (kk == 1) ? xv2.y : (kk == 2) ? xv2.z : xv2.w;
            float v3 = (kk == 0) ? xv3.x : (kk == 1) ? xv3.y : (kk == 2) ? xv3.z : xv3.w;
            acc[0]  += v0 * wa.x; acc[1]  += v0 * wa.y; acc[2]  += v0 * wa.z; acc[3]  += v0 * wa.w;
            acc[4]  += v0 * wb.x; acc[5]  += v0 * wb.y; acc[6]  += v0 * wb.z; acc[7]  += v0 * wb.w;
            acc[8]  += v1 * wa.x; acc[9]  += v1 * wa.y; acc[10] += v1 * wa.z; acc[11] += v1 * wa.w;
            acc[12] += v1 * wb.x; acc[13] += v1 * wb.y; acc[14] += v1 * wb.z; acc[15] += v1 * wb.w;
            acc[16] += v2 * wa.x; acc[17] += v2 * wa.y; acc[18] += v2 * wa.z; acc[19] += v2 * wa.w;
            acc[20] += v2 * wb.x; acc[21] += v2 * wb.y; acc[22] += v2 * wb.z; acc[23] += v2 * wb.w;
            acc[24] += v3 * wa.x; acc[25] += v3 * wa.y; acc[26] += v3 * wa.z; acc[27] += v3 * wa.w;
            acc[28] += v3 * wb.x; acc[29] += v3 * wb.y; acc[30] += v3 * wb.z; acc[31] += v3 * wb.w;
        }
    }
}

// per-block BN-stat partials into g_stats[stats_off..]; S >= 16*130 floats scratch.
__device__ __forceinline__ void stats_epi(float* S, const float* o, int stats_off,
                                          int ng, int fg, int node0, int tid) {
    float s[8], q[8];
#pragma unroll
    for (int j = 0; j < 8; j++) { s[j] = 0.0f; q[j] = 0.0f; }
#pragma unroll
    for (int i = 0; i < 4; i++) {
        if (node0 + ng * 4 + i < NN) {
#pragma unroll
            for (int j = 0; j < 8; j++) { float v = o[i*8+j]; s[j] += v; q[j] += v * v; }
        }
    }
#pragma unroll
    for (int j = 0; j < 8; j++) {
        S[ng * 130 + fg * 8 + j] = s[j];
        S[ng * 130 + 65 + fg * 8 + j] = q[j];
    }
    __syncthreads();
    int f = tid & 63, which = tid >> 6;
    float a = 0.0f;
#pragma unroll
    for (int g = 0; g < 16; g++) a += S[g * 130 + which * 65 + f];
    atomicAdd(&g_stats[stats_off + which * 64 + f], a);
}

// ---------------- L0 projection: y0 = x @ W1 (128->64) -> zc cols [64,128) ----------------
__global__ void __launch_bounds__(128) gemm1_kernel(
    const float* __restrict__ x, const float* __restrict__ W1, float* zc)
{
    __shared__ float Ws[4096];
    __shared__ float Xs[64 * 68];
    const int tid = threadIdx.x, fg = tid & 7, ng = tid >> 3;
    const int node0 = blockIdx.x * 64;

    float acc[32];
#pragma unroll
    for (int q = 0; q < 32; q++) acc[q] = 0.0f;

    for (int kc = 0; kc < 2; kc++) {
        __syncthreads();
        stage_w(Ws, W1 + kc * 64 * 64, tid);
        stage_x(Xs, x + kc * 64, DIN, node0, tid);
        __syncthreads();
        gemm_core(Xs, Ws, ng, fg, acc);
    }

#pragma unroll
    for (int i = 0; i < 4; i++) {
        int node = node0 + ng * 4 + i;
        if (node < NN) {
            float* row = zc + (long long)node * ZS + 64;
            *reinterpret_cast<float4*>(row + fg * 8) =
                make_float4(acc[i*8+0], acc[i*8+1], acc[i*8+2], acc[i*8+3]);
            *reinterpret_cast<float4*>(row + fg * 8 + 4) =
                make_float4(acc[i*8+4], acc[i*8+5], acc[i*8+6], acc[i*8+7]);
        }
    }
}

// ---------------- L0 MLP tail: h = relu( relu(agg+b1) @ W2 + b2 ), in place + stats ------
__global__ void __launch_bounds__(128) mlp0_kernel(
    float* zc, int col, int stats_off,
    const float* __restrict__ W2, const float* __restrict__ b1,
    const float* __restrict__ b2)
{
    __shared__ float Ws[4096];
    __shared__ float Xs[64 * 68];
    const int tid = threadIdx.x, fg = tid & 7, ng = tid >> 3;
    const int node0 = blockIdx.x * 64;

    stage_w(Ws, W2, tid);
    {   // Xs = relu(agg + b1)
        int row = tid >> 1, part = tid & 1;
        int gn = node0 + row; if (gn >= NN) gn = NN - 1;
        const float4* src = reinterpret_cast<const float4*>(zc + (long long)gn * ZS + col);
        float4* dst = reinterpret_cast<float4*>(Xs + row * 68);
#pragma unroll
        for (int q = 0; q < 8; q++) {
            int c4 = part * 8 + q;
            float4 a = src[c4];
            float4 bb = reinterpret_cast<const float4*>(b1)[c4];
            dst[c4] = make_float4(fmaxf(a.x + bb.x, 0.0f), fmaxf(a.y + bb.y, 0.0f),
                                  fmaxf(a.z + bb.z, 0.0f), fmaxf(a.w + bb.w, 0.0f));
        }
    }
    __syncthreads();

    float acc[32];
    {
        float4 ba = reinterpret_cast<const float4*>(b2)[fg * 2];
        float4 bb = reinterpret_cast<const float4*>(b2)[fg * 2 + 1];
#pragma unroll
        for (int i = 0; i < 4; i++) {
            acc[i*8+0] = ba.x; acc[i*8+1] = ba.y; acc[i*8+2] = ba.z; acc[i*8+3] = ba.w;
            acc[i*8+4] = bb.x; acc[i*8+5] = bb.y; acc[i*8+6] = bb.z; acc[i*8+7] = bb.w;
        }
    }
    gemm_core(Xs, Ws, ng, fg, acc);
#pragma unroll
    for (int q = 0; q < 32; q++) acc[q] = fmaxf(acc[q], 0.0f);

#pragma unroll
    for (int i = 0; i < 4; i++) {
        int node = node0 + ng * 4 + i;
        if (node < NN) {
            float* row = zc + (long long)node * ZS + col;
            *reinterpret_cast<float4*>(row + fg * 8) =
                make_float4(acc[i*8+0], acc[i*8+1], acc[i*8+2], acc[i*8+3]);
            *reinterpret_cast<float4*>(row + fg * 8 + 4) =
                make_float4(acc[i*8+4], acc[i*8+5], acc[i*8+6], acc[i*8+7]);
        }
    }
    __syncthreads();
    stats_epi(Ws, acc, stats_off, ng, fg, node0, tid);
}

// ---------------- L1/L2 MLP: h = relu( relu(agg@W1+b1) @ W2 + b2 ) + stats ----------------
__global__ void __launch_bounds__(128) mlp2_kernel(
    float* zc, int in_col, int out_col, int stats_off,
    const float* __restrict__ W1, const float* __restrict__ b1,
    const float* __restrict__ W2, const float* __restrict__ b2)
{
    __shared__ float Ws[4096];
    __shared__ float Xs[64 * 68];
    const int tid = threadIdx.x, fg = tid & 7, ng = tid >> 3;
    const int node0 = blockIdx.x * 64;

    stage_w(Ws, W1, tid);
    stage_x(Xs, zc + in_col, ZS, node0, tid);
    __syncthreads();

    float acc[32];
#pragma unroll
    for (int q = 0; q < 32; q++) acc[q] = 0.0f;
    gemm_core(Xs, Ws, ng, fg, acc);
    __syncthreads();

    {
        float4 ba = reinterpret_cast<const float4*>(b1)[fg * 2];
        float4 bb = reinterpret_cast<const float4*>(b1)[fg * 2 + 1];
#pragma unroll
        for (int i = 0; i < 4; i++) {
            float* hr = Xs + (ng * 4 + i) * 68 + fg * 8;
            *reinterpret_cast<float4*>(hr) =
                make_float4(fmaxf(acc[i*8+0]+ba.x,0.f), fmaxf(acc[i*8+1]+ba.y,0.f),
                            fmaxf(acc[i*8+2]+ba.z,0.f), fmaxf(acc[i*8+3]+ba.w,0.f));
            *reinterpret_cast<float4*>(hr + 4) =
                make_float4(fmaxf(acc[i*8+4]+bb.x,0.f), fmaxf(acc[i*8+5]+bb.y,0.f),
                            fmaxf(acc[i*8+6]+bb.z,0.f), fmaxf(acc[i*8+7]+bb.w,0.f));
        }
    }
    stage_w(Ws, W2, tid);
    __syncthreads();

    {
        float4 ba = reinterpret_cast<const float4*>(b2)[fg * 2];
        float4 bb = reinterpret_cast<const float4*>(b2)[fg * 2 + 1];
#pragma unroll
        for (int i = 0; i < 4; i++) {
            acc[i*8+0] = ba.x; acc[i*8+1] = ba.y; acc[i*8+2] = ba.z; acc[i*8+3] = ba.w;
            acc[i*8+4] = bb.x; acc[i*8+5] = bb.y; acc[i*8+6] = bb.z; acc[i*8+7] = bb.w;
        }
    }
    gemm_core(Xs, Ws, ng, fg, acc);
#pragma unroll
    for (int q = 0; q < 32; q++) acc[q] = fmaxf(acc[q], 0.0f);

#pragma unroll
    for (int i = 0; i < 4; i++) {
        int node = node0 + ng * 4 + i;
        if (node < NN) {
            float* row = zc + (long long)node * ZS + out_col;
            *reinterpret_cast<float4*>(row + fg * 8) =
                make_float4(acc[i*8+0], acc[i*8+1], acc[i*8+2], acc[i*8+3]);
            *reinterpret_cast<float4*>(row + fg * 8 + 4) =
                make_float4(acc[i*8+4], acc[i*8+5], acc[i*8+6], acc[i*8+7]);
        }
    }
    __syncthreads();
    stats_epi(Ws, acc, stats_off, ng, fg, node0, tid);
}

// ---------------- L2 RED scatter (agg col init'd with z1 copy by bn_apply) ----------------
__global__ void scatter_kernel(float* zc, int src_col, int agg_col,
                               const void* __restrict__ ei) {
    int gtid = blockIdx.x * 256 + threadIdx.x;
    int e = gtid >> 3;
    int c = gtid & 7;
    if (e >= EE) return;
    int is64 = g_is64;
    long long s = ldidx(ei, e, is64);
    long long d = ldidx(ei, (long long)EE + e, is64);
    const float4* sp = reinterpret_cast<const float4*>(zc + s * ZS + src_col);
    float4 v0 = sp[c];
    float4 v1 = sp[c + 8];
    float* dp = zc + d * ZS + agg_col;
    red4(dp + c * 4, v0);
    red4(dp + 32 + c * 4, v1);
}

// ---------------- BN apply: finalize (per block, from stats) + normalize + pool + copy ----
__global__ void bn_apply_kernel(float* zc, int col_off, int copy_off, int stats_off,
                                const void* __restrict__ batch,
                                float* __restrict__ pool,
                                const float* __restrict__ gam,
                                const float* __restrict__ bet)
{
    __shared__ __align__(16) float sc_s[64], sh_s[64];
    int t = threadIdx.x;
    if (t < 64) {
        float mean = g_stats[stats_off + t] * (1.0f / NN);
        float var = g_stats[stats_off + 64 + t] * (1.0f / NN) - mean * mean;
        var = fmaxf(var, 0.0f);
        float s = gam[t] * rsqrtf(var + BN_EPS);
        sc_s[t] = s;
        sh_s[t] = bet[t] - mean * s;
    }
    __syncthreads();

    int gt = blockIdx.x * 256 + t;
    int n = gt >> 4;
    int c = gt & 15;
    if (n >= NN) return;
    int is64 = g_is64;
    float* row = zc + (long long)n * ZS;
    float4 h4 = *reinterpret_cast<float4*>(row + col_off + c * 4);
    float4 sc = *reinterpret_cast<const float4*>(sc_s + c * 4);
    float4 sh = *reinterpret_cast<const float4*>(sh_s + c * 4);
    float4 z;
    z.x = h4.x * sc.x + sh.x;
    z.y = h4.y * sc.y + sh.y;
    z.z = h4.z * sc.z + sh.z;
    z.w = h4.w * sc.w + sh.w;
    *reinterpret_cast<float4*>(row + col_off + c * 4) = z;
    if (copy_off >= 0)
        *reinterpret_cast<float4*>(row + copy_off + c * 4) = z;
    long long b = ldidx(batch, n, is64);
    red4(pool + b * ZS + col_off + c * 4, z);
}

// ---------------- launch ----------------
extern "C" void kernel_launch(void* const* d_in, const int* in_sizes, int n_in,
                              void* d_out, int out_size)
{
    const float* x     = (const float*)d_in[0];
    const void*  ei    = d_in[1];
    const void*  batch = d_in[2];
    const float* W1_0  = (const float*)d_in[3];
    const float* b1_0  = (const float*)d_in[4];
    const float* W2_0  = (const float*)d_in[5];
    const float* b2_0  = (const float*)d_in[6];
    const float* bn_g0 = (const float*)d_in[7];
    const float* bn_b0 = (const float*)d_in[8];
    const float* W1_r  = (const float*)d_in[9];
    const float* b1_r  = (const float*)d_in[10];
    const float* W2_r  = (const float*)d_in[11];
    const float* b2_r  = (const float*)d_in[12];
    const float* bn_gr = (const float*)d_in[13];
    const float* bn_br = (const float*)d_in[14];

    float* zc   = (float*)d_out;
    float* pool = zc + (long long)NN * ZS;

    const int gemm_grid = (NN + 63) / 64;            // 782
    const int edge_grid = (EE + 255) / 256;          // 3125
    const int gath_grid = (NN * 32 + 255) / 256;     // 6250
    const int scat_grid = (EE * 8) / 256;            // 25000
    const int bn_grid   = (NN * 16 + 255) / 256;     // 3125

    // setup + dst-sort of edges (list lives in zc cols 128.. until bn_apply(L1))
    setup_kernel<<<256, 256>>>(zc, pool, (const long long*)ei);
    hist_kernel<<<edge_grid, 256>>>(zc, ei);
    scan_partials_kernel<<<SCAN_NB, 256>>>(zc);
    scan_top_kernel<<<1, 256>>>(zc);
    scan_apply_kernel<<<SCAN_NB, 256>>>(zc);
    place_kernel<<<edge_grid, 256>>>(zc, ei);

    // ---- layer 0: y0 = x@W1 -> col 64; gather y0 -> agg @ col 0; MLP in place @ 0 ----
    gemm1_kernel<<<gemm_grid, 128>>>(x, W1_0, zc);
    gather_kernel<<<gath_grid, 256>>>(zc, 64, 0);
    mlp0_kernel<<<gemm_grid, 128>>>(zc, 0, 0, W2_0, b1_0, b2_0);
    bn_apply_kernel<<<bn_grid, 256>>>(zc, 0, -1, 0, batch, pool, bn_g0, bn_b0);

    // ---- layer 1: gather z0 (col 0) -> agg @ col 64; MLP in place @ 64 ----
    gather_kernel<<<gath_grid, 256>>>(zc, 0, 64);
    mlp2_kernel<<<gemm_grid, 128>>>(zc, 64, 64, 128, W1_r, b1_r, W2_r, b2_r);
    bn_apply_kernel<<<bn_grid, 256>>>(zc, 64, 128, 128, batch, pool, bn_gr, bn_br);  // copy z1->128

    // ---- layer 2: RED scatter (z1 @64 -> agg @128) + MLP in place @128 ----
    scatter_kernel<<<scat_grid, 256>>>(zc, 64, 128, ei);
    mlp2_kernel<<<gemm_grid, 128>>>(zc, 128, 128, 256,
                                    W1_r + (size_t)HH * HH, b1_r + HH,
                                    W2_r + (size_t)HH * HH, b2_r + HH);
    bn_apply_kernel<<<bn_grid, 256>>>(zc, 128, -1, 256, batch, pool, bn_gr + HH, bn_br + HH);

    (void)in_sizes; (void)n_in; (void)out_size;
}

// round 14
// speedup vs baseline: 1.2360x; 1.0059x over previous
#include <cuda_runtime.h>
#include <cuda_bf16.h>
#include <stdint.h>

// Problem constants
#define NN   50000
#define EE   800000
#define GG   512
#define DIN  128
#define HH   64
#define ZS   192              // L*H, row stride of z_cat and pool
#define BN_EPS 1e-5f

// scratch layout inside zc cols [128,192) viewed as int32 (free until bn_apply(L1))
#define SCR_A 0          // counts -> cursor, NN ints
#define SCR_B 51200      // offsets, NN+1 ints
#define SCR_P 102400     // scan partials, 196 ints
#define SCR_L 102656     // dst-sorted src list, EE ints (ends 902656 < 3.2M)
#define SCAN_NB 196      // ceil(NN/256)

typedef unsigned long long u64;

// ---------------- tiny device globals (~2 KB; device-code access only) ----------------
__device__ __align__(16) float g_stats[384];   // per layer: [0:64) sum, [64:128) sumsq
__device__ int g_is64;

// ---------------- helpers ----------------
__device__ __forceinline__ void red4(float* p, float4 v) {
    atomicAdd(reinterpret_cast<float4*>(p), v);
}

__device__ __forceinline__ long long ldidx(const void* p, long long i, int is64) {
    if (is64) return ((const long long*)p)[i];
    return (long long)((const int*)p)[i];
}

// strided scratch accessor: int slot i -> zc[(i/64)*192 + 128 + i%64]
__device__ __forceinline__ int* scr(float* zc, int i) {
    return reinterpret_cast<int*>(zc) + (long long)(i >> 6) * ZS + 128 + (i & 63);
}

// ---- packed f32x2 helpers (Blackwell FFMA2; PTX ISA 8.6 sm_100+) ----
__device__ __forceinline__ u64 pk2(float x) {
    u64 r; asm("mov.b64 %0, {%1, %1};" : "=l"(r) : "f"(x)); return r;
}
__device__ __forceinline__ void up2(u64 v, float& lo, float& hi) {
    asm("mov.b64 {%0, %1}, %2;" : "=f"(lo), "=f"(hi) : "l"(v));
}
__device__ __forceinline__ void fma2(u64& d, u64 a, u64 b) {
    asm("fma.rn.f32x2 %0, %1, %2, %0;" : "+l"(d) : "l"(a), "l"(b));
}

// ---------------- setup: zero pool + stats + counts, detect index dtype ----------------
__global__ void setup_kernel(float* zc, float* pool, const long long* ei) {
    int gt = blockIdx.x * 256 + threadIdx.x;
    for (int i = gt; i < GG * ZS; i += gridDim.x * 256) pool[i] = 0.0f;
    for (int i = gt; i < NN; i += gridDim.x * 256) *scr(zc, SCR_A + i) = 0;
    if (blockIdx.x == 0) {
        if (threadIdx.x < 128) {
            g_stats[threadIdx.x] = 0.0f;
            g_stats[threadIdx.x + 128] = 0.0f;
            g_stats[threadIdx.x + 256] = 0.0f;
        }
        if (threadIdx.x == 0) {
            int ok = 1;
            for (int i = 0; i < 16; i++) {
                long long v = ei[i];
                if (v < 0 || v >= NN) ok = 0;
            }
            g_is64 = ok;
        }
    }
}

// ---------------- counting sort of edges by dst (multi-block scan) ----------------
// 4 edges per thread: 4 independent atomic chains in flight (latency hiding).
__global__ void hist_kernel(float* zc, const void* __restrict__ ei) {
    int base = (blockIdx.x * 256 + threadIdx.x) * 4;
    int is64 = g_is64;
#pragma unroll
    for (int j = 0; j < 4; j++) {
        int e = base + j;
        if (e < EE) {
            int d = (int)ldidx(ei, (long long)EE + e, is64);
            atomicAdd(scr(zc, SCR_A + d), 1);
        }
    }
}

__device__ __forceinline__ int block_incl_scan(int* sh, int t, int v) {
    sh[t] = v;
    __syncthreads();
#pragma unroll
    for (int s = 1; s < 256; s <<= 1) {
        int add = (t >= s) ? sh[t - s] : 0;
        __syncthreads();
        sh[t] += add;
        __syncthreads();
    }
    return sh[t];
}

__global__ void scan_partials_kernel(float* zc) {
    __shared__ int sh[256];
    int t = threadIdx.x;
    int i = blockIdx.x * 256 + t;
    int c = (i < NN) ? *scr(zc, SCR_A + i) : 0;
    sh[t] = c;
    __syncthreads();
    for (int s = 128; s > 0; s >>= 1) {
        if (t < s) sh[t] += sh[t + s];
        __syncthreads();
    }
    if (t == 0) *scr(zc, SCR_P + blockIdx.x) = sh[0];
}

__global__ void scan_top_kernel(float* zc) {
    __shared__ int sh[256];
    int t = threadIdx.x;
    int v = (t < SCAN_NB) ? *scr(zc, SCR_P + t) : 0;
    int inc = block_incl_scan(sh, t, v);
    if (t < SCAN_NB) *scr(zc, SCR_P + t) = inc - v;   // exclusive
    if (t == 0) *scr(zc, SCR_B + NN) = EE;
}

__global__ void scan_apply_kernel(float* zc) {
    __shared__ int sh[256];
    int t = threadIdx.x;
    int i = blockIdx.x * 256 + t;
    int c = (i < NN) ? *scr(zc, SCR_A + i) : 0;
    int inc = block_incl_scan(sh, t, c);
    int base = *scr(zc, SCR_P + blockIdx.x);
    if (i < NN) {
        int off = base + inc - c;      // exclusive prefix
        *scr(zc, SCR_B + i) = off;     // offsets
        *scr(zc, SCR_A + i) = off;     // cursor init
    }
}

__global__ void place_kernel(float* zc, const void* __restrict__ ei) {
    int base = (blockIdx.x * 256 + threadIdx.x) * 4;
    int is64 = g_is64;
#pragma unroll
    for (int j = 0; j < 4; j++) {
        int e = base + j;
        if (e < EE) {
            int s = (int)ldidx(ei, e, is64);
            int d = (int)ldidx(ei, (long long)EE + e, is64);
            int pos = atomicAdd(scr(zc, SCR_A + d), 1);
            *scr(zc, SCR_L + pos) = s;
        }
    }
}

// ---------------- gather: one warp per dst row; agg[n] = src[n] + sum src[list] ----------
__global__ void __launch_bounds__(256) gather_kernel(float* zc, int src_col, int agg_col) {
    int n = (blockIdx.x * 256 + threadIdx.x) >> 5;
    int lane = threadIdx.x & 31;
    if (n >= NN) return;
    const float* self = zc + (long long)n * ZS + src_col;
    float a0 = self[lane], a1 = self[lane + 32];
    int start = *scr(zc, SCR_B + n);
    int end   = *scr(zc, SCR_B + n + 1);
    float p0 = 0, p1 = 0, q0 = 0, q1 = 0, u0 = 0, u1 = 0, t0 = 0, t1 = 0;
    int e = start;
    for (; e + 3 < end; e += 4) {
        int s0 = *scr(zc, SCR_L + e);
        int s1 = *scr(zc, SCR_L + e + 1);
        int s2 = *scr(zc, SCR_L + e + 2);
        int s3 = *scr(zc, SCR_L + e + 3);
        const float* r0 = zc + (long long)s0 * ZS + src_col;
        const float* r1 = zc + (long long)s1 * ZS + src_col;
        const float* r2 = zc + (long long)s2 * ZS + src_col;
        const float* r3 = zc + (long long)s3 * ZS + src_col;
        p0 += r0[lane]; p1 += r0[lane + 32];
        q0 += r1[lane]; q1 += r1[lane + 32];
        u0 += r2[lane]; u1 += r2[lane + 32];
        t0 += r3[lane]; t1 += r3[lane + 32];
    }
    for (; e < end; e++) {
        int s0 = *scr(zc, SCR_L + e);
        const float* r0 = zc + (long long)s0 * ZS + src_col;
        p0 += r0[lane]; p1 += r0[lane + 32];
    }
    a0 += (p0 + q0) + (u0 + t0);
    a1 += (p1 + q1) + (u1 + t1);
    float* out = zc + (long long)n * ZS + agg_col;
    out[lane] = a0;
    out[lane + 32] = a1;
}

// ======================= GEMM building blocks (FFMA2 core) =======================
// Block 128 threads, 64 nodes. Thread (ng=tid>>3, fg=tid&7) owns 4 nodes x 8 features,
// accumulated as 16 packed f32x2 (feature pairs): acc2[node*4 + fpair].

__device__ __forceinline__ void stage_w(float* Ws, const float* __restrict__ W, int tid) {
    for (int i = tid; i < 1024; i += 128)
        reinterpret_cast<float4*>(Ws)[i] = reinterpret_cast<const float4*>(W)[i];
}

__device__ __forceinline__ void stage_x(float* Xs, const float* __restrict__ gx,
                                        int zstride, int node0, int tid) {
    int row = tid >> 1, part = tid & 1;
    int gn = node0 + row; if (gn >= NN) gn = NN - 1;
    const float4* src = reinterpret_cast<const float4*>(gx + (long long)gn * zstride);
    float4* dst = reinterpret_cast<float4*>(Xs + row * 68);
#pragma unroll
    for (int q = 0; q < 8; q++) dst[part * 8 + q] = src[part * 8 + q];
}

// acc2 += Xs(64x64) @ Ws(64x64) for this thread's 4-node x 8-feature tile (FFMA2)
__device__ __forceinline__ void gemm_core2(const float* Xs, const float* Ws,
                                           int ng, int fg, u64* acc2) {
#pragma unroll
    for (int k4 = 0; k4 < 16; k4++) {
        float4 xv0 = *reinterpret_cast<const float4*>(Xs + (ng * 4 + 0) * 68 + k4 * 4);
        float4 xv1 = *reinterpret_cast<const float4*>(Xs + (ng * 4 + 1) * 68 + k4 * 4);
        float4 xv2 = *reinterpret_cast<const float4*>(Xs + (ng * 4 + 2) * 68 + k4 * 4);
        float4 xv3 = *reinterpret_cast<const float4*>(Xs + (ng * 4 + 3) * 68 + k4 * 4);
#pragma unroll
        for (int kk = 0; kk < 4; kk++) {
            const ulonglong2* wr = reinterpret_cast<const ulonglong2*>(
                Ws + (k4 * 4 + kk) * 64 + fg * 8);
            ulonglong2 wa = wr[0];   // feature pairs (0,1),(2,3)
            ulonglong2 wb = wr[1];   // feature pairs (4,5),(6,7)
            float v0 = (kk == 0) ? xv0.x : (kk == 1) ? xv0.y : (kk == 2) ? xv0.z : xv0.w;
            float v1 = (kk == 0) ? xv1.x : (kk == 1) ? xv1.y : (kk == 2) ? xv1.z : xv1.w;
            float v2 = (kk == 0) ? xv2.x : (kk == 1) ? xv2.y : (kk == 2) ? xv2.z : xv2.w;
            float v3 = (kk == 0) ? xv3.x : (kk == 1) ? xv3.y : (kk == 2) ? xv3.z : xv3.w;
            u64 x0 = pk2(v0), x1 = pk2(v1), x2 = pk2(v2), x3 = pk2(v3);
            fma2(acc2[0],  x0, wa.x); fma2(acc2[1],  x0, wa.y);
            fma2(acc2[2],  x0, wb.x); fma2(acc2[3],  x0, wb.y);
            fma2(acc2[4],  x1, wa.x); fma2(acc2[5],  x1, wa.y);
            fma2(acc2[6],  x1, wb.x); fma2(acc2[7],  x1, wb.y);
            fma2(acc2[8],  x2, wa.x); fma2(acc2[9],  x2, wa.y);
            fma2(acc2[10], x2, wb.x); fma2(acc2[11], x2, wb.y);
            fma2(acc2[12], x3, wa.x); fma2(acc2[13], x3, wa.y);
            fma2(acc2[14], x3, wb.x); fma2(acc2[15], x3, wb.y);
        }
    }
}

// unpack acc2 -> o[32] (i*8+j layout) with relu
__device__ __forceinline__ void unpack_relu(const u64* acc2, float* o) {
#pragma unroll
    for (int i = 0; i < 4; i++) {
#pragma unroll
        for (int jp = 0; jp < 4; jp++) {
            float lo, hi;
            up2(acc2[i * 4 + jp], lo, hi);
            o[i * 8 + jp * 2]     = fmaxf(lo, 0.0f);
            o[i * 8 + jp * 2 + 1] = fmaxf(hi, 0.0f);
        }
    }
}

__device__ __forceinline__ void bias_init2(u64* acc2, const float* __restrict__ b, int fg) {
    const ulonglong2* bp = reinterpret_cast<const ulonglong2*>(b + fg * 8);
    ulonglong2 ba = bp[0], bb = bp[1];
#pragma unroll
    for (int i = 0; i < 4; i++) {
        acc2[i * 4 + 0] = ba.x; acc2[i * 4 + 1] = ba.y;
        acc2[i * 4 + 2] = bb.x; acc2[i * 4 + 3] = bb.y;
    }
}

__device__ __forceinline__ void store_o(float* zc, int node0, int col,
                                        int ng, int fg, const float* o) {
#pragma unroll
    for (int i = 0; i < 4; i++) {
        int node = node0 + ng * 4 + i;
        if (node < NN) {
            float* row = zc + (long long)node * ZS + col;
            *reinterpret_cast<float4*>(row + fg * 8) =
                make_float4(o[i*8+0], o[i*8+1], o[i*8+2], o[i*8+3]);
            *reinterpret_cast<float4*>(row + fg * 8 + 4) =
                make_float4(o[i*8+4], o[i*8+5], o[i*8+6], o[i*8+7]);
        }
    }
}

// per-block BN-stat partials into g_stats[stats_off..]; S >= 16*130 floats scratch.
__device__ __forceinline__ void stats_epi(float* S, const float* o, int stats_off,
                                          int ng, int fg, int node0, int tid) {
    float s[8], q[8];
#pragma unroll
    for (int j = 0; j < 8; j++) { s[j] = 0.0f; q[j] = 0.0f; }
#pragma unroll
    for (int i = 0; i < 4; i++) {
        if (node0 + ng * 4 + i < NN) {
#pragma unroll
            for (int j = 0; j < 8; j++) { float v = o[i*8+j]; s[j] += v; q[j] += v * v; }
        }
    }
#pragma unroll
    for (int j = 0; j < 8; j++) {
        S[ng * 130 + fg * 8 + j] = s[j];
        S[ng * 130 + 65 + fg * 8 + j] = q[j];
    }
    __syncthreads();
    int f = tid & 63, which = tid >> 6;
    float a = 0.0f;
#pragma unroll
    for (int g = 0; g < 16; g++) a += S[g * 130 + which * 65 + f];
    atomicAdd(&g_stats[stats_off + which * 64 + f], a);
}

// ---------------- L0 projection: y0 = x @ W1 (128->64) -> zc cols [64,128) ----------------
__global__ void __launch_bounds__(128) gemm1_kernel(
    const float* __restrict__ x, const float* __restrict__ W1, float* zc)
{
    __shared__ float Ws[4096];
    __shared__ float Xs[64 * 68];
    const int tid = threadIdx.x, fg = tid & 7, ng = tid >> 3;
    const int node0 = blockIdx.x * 64;

    u64 acc2[16];
#pragma unroll
    for (int q = 0; q < 16; q++) acc2[q] = 0ULL;

    for (int kc = 0; kc < 2; kc++) {
        __syncthreads();
        stage_w(Ws, W1 + kc * 64 * 64, tid);
        stage_x(Xs, x + kc * 64, DIN, node0, tid);
        __syncthreads();
        gemm_core2(Xs, Ws, ng, fg, acc2);
    }

    // no relu: unpack raw
    float o[32];
#pragma unroll
    for (int i = 0; i < 4; i++)
#pragma unroll
        for (int jp = 0; jp < 4; jp++)
            up2(acc2[i * 4 + jp], o[i * 8 + jp * 2], o[i * 8 + jp * 2 + 1]);
    store_o(zc, node0, 64, ng, fg, o);
}

// ---------------- L0 MLP tail: h = relu( relu(agg+b1) @ W2 + b2 ), in place + stats ------
__global__ void __launch_bounds__(128) mlp0_kernel(
    float* zc, int col, int stats_off,
    const float* __restrict__ W2, const float* __restrict__ b1,
    const float* __restrict__ b2)
{
    __shared__ float Ws[4096];
    __shared__ float Xs[64 * 68];
    const int tid = threadIdx.x, fg = tid & 7, ng = tid >> 3;
    const int node0 = blockIdx.x * 64;

    stage_w(Ws, W2, tid);
    {   // Xs = relu(agg + b1)
        int row = tid >> 1, part = tid & 1;
        int gn = node0 + row; if (gn >= NN) gn = NN - 1;
        const float4* src = reinterpret_cast<const float4*>(zc + (long long)gn * ZS + col);
        float4* dst = reinterpret_cast<float4*>(Xs + row * 68);
#pragma unroll
        for (int q = 0; q < 8; q++) {
            int c4 = part * 8 + q;
            float4 a = src[c4];
            float4 bb = reinterpret_cast<const float4*>(b1)[c4];
            dst[c4] = make_float4(fmaxf(a.x + bb.x, 0.0f), fmaxf(a.y + bb.y, 0.0f),
                                  fmaxf(a.z + bb.z, 0.0f), fmaxf(a.w + bb.w, 0.0f));
        }
    }
    __syncthreads();

    u64 acc2[16];
    bias_init2(acc2, b2, fg);
    gemm_core2(Xs, Ws, ng, fg, acc2);

    float o[32];
    unpack_relu(acc2, o);
    store_o(zc, node0, col, ng, fg, o);
    __syncthreads();
    stats_epi(Ws, o, stats_off, ng, fg, node0, tid);
}

// ---------------- L1/L2 MLP: h = relu( relu(agg@W1+b1) @ W2 + b2 ) + stats ----------------
__global__ void __launch_bounds__(128) mlp2_kernel(
    float* zc, int in_col, int out_col, int stats_off,
    const float* __restrict__ W1, const float* __restrict__ b1,
    const float* __restrict__ W2, const float* __restrict__ b2)
{
    __shared__ float Ws[4096];
    __shared__ float Xs[64 * 68];
    const int tid = threadIdx.x, fg = tid & 7, ng = tid >> 3;
    const int node0 = blockIdx.x * 64;

    stage_w(Ws, W1, tid);
    stage_x(Xs, zc + in_col, ZS, node0, tid);
    __syncthreads();

    // phase 1: acc2 = agg @ W1
    u64 acc2[16];
#pragma unroll
    for (int q = 0; q < 16; q++) acc2[q] = 0ULL;
    gemm_core2(Xs, Ws, ng, fg, acc2);
    __syncthreads();   // phase-1 reads of Ws/Xs complete

    // h1 = relu(acc2 + b1) -> Xs (own tiles, float2 stores), then stage W2
    {
        const ulonglong2* bp = reinterpret_cast<const ulonglong2*>(b1 + fg * 8);
        ulonglong2 ca = bp[0], cb = bp[1];
        u64 bb4[4] = {ca.x, ca.y, cb.x, cb.y};
#pragma unroll
        for (int i = 0; i < 4; i++) {
#pragma unroll
            for (int jp = 0; jp < 4; jp++) {
                float lo, hi, blo, bhi;
                up2(acc2[i * 4 + jp], lo, hi);
                up2(bb4[jp], blo, bhi);
                lo = fmaxf(lo + blo, 0.0f);
                hi = fmaxf(hi + bhi, 0.0f);
                *reinterpret_cast<float2*>(Xs + (ng * 4 + i) * 68 + fg * 8 + jp * 2) =
                    make_float2(lo, hi);
            }
        }
    }
    stage_w(Ws, W2, tid);
    __syncthreads();

    // phase 2: acc2 = h1 @ W2 + b2
    bias_init2(acc2, b2, fg);
    gemm_core2(Xs, Ws, ng, fg, acc2);

    float o[32];
    unpack_relu(acc2, o);
    store_o(zc, node0, out_col, ng, fg, o);
    __syncthreads();
    stats_epi(Ws, o, stats_off, ng, fg, node0, tid);
}

// ---------------- L2 RED scatter (agg col init'd with z1 copy by bn_apply) ----------------
__global__ void scatter_kernel(float* zc, int src_col, int agg_col,
                               const void* __restrict__ ei) {
    int gtid = blockIdx.x * 256 + threadIdx.x;
    int e = gtid >> 3;
    int c = gtid & 7;
    if (e >= EE) return;
    int is64 = g_is64;
    long long s = ldidx(ei, e, is64);
    long long d = ldidx(ei, (long long)EE + e, is64);
    const float4* sp = reinterpret_cast<const float4*>(zc + s * ZS + src_col);
    float4 v0 = sp[c];
    float4 v1 = sp[c + 8];
    float* dp = zc + d * ZS + agg_col;
    red4(dp + c * 4, v0);
    red4(dp + 32 + c * 4, v1);
}

// ---------------- BN apply: finalize (per block, from stats) + normalize + pool + copy ----
__global__ void bn_apply_kernel(float* zc, int col_off, int copy_off, int stats_off,
                                const void* __restrict__ batch,
                                float* __restrict__ pool,
                                const float* __restrict__ gam,
                                const float* __restrict__ bet)
{
    __shared__ __align__(16) float sc_s[64], sh_s[64];
    int t = threadIdx.x;
    if (t < 64) {
        float mean = g_stats[stats_off + t] * (1.0f / NN);
        float var = g_stats[stats_off + 64 + t] * (1.0f / NN) - mean * mean;
        var = fmaxf(var, 0.0f);
        float s = gam[t] * rsqrtf(var + BN_EPS);
        sc_s[t] = s;
        sh_s[t] = bet[t] - mean * s;
    }
    __syncthreads();

    int gt = blockIdx.x * 256 + t;
    int n = gt >> 4;
    int c = gt & 15;
    if (n >= NN) return;
    int is64 = g_is64;
    float* row = zc + (long long)n * ZS;
    float4 h4 = *reinterpret_cast<float4*>(row + col_off + c * 4);
    float4 sc = *reinterpret_cast<const float4*>(sc_s + c * 4);
    float4 sh = *reinterpret_cast<const float4*>(sh_s + c * 4);
    float4 z;
    z.x = h4.x * sc.x + sh.x;
    z.y = h4.y * sc.y + sh.y;
    z.z = h4.z * sc.z + sh.z;
    z.w = h4.w * sc.w + sh.w;
    *reinterpret_cast<float4*>(row + col_off + c * 4) = z;
    if (copy_off >= 0)
        *reinterpret_cast<float4*>(row + copy_off + c * 4) = z;
    long long b = ldidx(batch, n, is64);
    red4(pool + b * ZS + col_off + c * 4, z);
}

// ---------------- launch ----------------
extern "C" void kernel_launch(void* const* d_in, const int* in_sizes, int n_in,
                              void* d_out, int out_size)
{
    const float* x     = (const float*)d_in[0];
    const void*  ei    = d_in[1];
    const void*  batch = d_in[2];
    const float* W1_0  = (const float*)d_in[3];
    const float* b1_0  = (const float*)d_in[4];
    const float* W2_0  = (const float*)d_in[5];
    const float* b2_0  = (const float*)d_in[6];
    const float* bn_g0 = (const float*)d_in[7];
    const float* bn_b0 = (const float*)d_in[8];
    const float* W1_r  = (const float*)d_in[9];
    const float* b1_r  = (const float*)d_in[10];
    const float* W2_r  = (const float*)d_in[11];
    const float* b2_r  = (const float*)d_in[12];
    const float* bn_gr = (const float*)d_in[13];
    const float* bn_br = (const float*)d_in[14];

    float* zc   = (float*)d_out;
    float* pool = zc + (long long)NN * ZS;

    const int gemm_grid = (NN + 63) / 64;            // 782
    const int edge4_grid = (EE + 1023) / 1024;       // 782 (4 edges/thread)
    const int gath_grid = (NN * 32 + 255) / 256;     // 6250
    const int scat_grid = (EE * 8) / 256;            // 25000
    const int bn_grid   = (NN * 16 + 255) / 256;     // 3125

    // setup + dst-sort of edges (list lives in zc cols 128.. until bn_apply(L1))
    setup_kernel<<<256, 256>>>(zc, pool, (const long long*)ei);
    hist_kernel<<<edge4_grid, 256>>>(zc, ei);
    scan_partials_kernel<<<SCAN_NB, 256>>>(zc);
    scan_top_kernel<<<1, 256>>>(zc);
    scan_apply_kernel<<<SCAN_NB, 256>>>(zc);
    place_kernel<<<edge4_grid, 256>>>(zc, ei);

    // ---- layer 0: y0 = x@W1 -> col 64; gather y0 -> agg @ col 0; MLP in place @ 0 ----
    gemm1_kernel<<<gemm_grid, 128>>>(x, W1_0, zc);
    gather_kernel<<<gath_grid, 256>>>(zc, 64, 0);
    mlp0_kernel<<<gemm_grid, 128>>>(zc, 0, 0, W2_0, b1_0, b2_0);
    bn_apply_kernel<<<bn_grid, 256>>>(zc, 0, -1, 0, batch, pool, bn_g0, bn_b0);

    // ---- layer 1: gather z0 (col 0) -> agg @ col 64; MLP in place @ 64 ----
    gather_kernel<<<gath_grid, 256>>>(zc, 0, 64);
    mlp2_kernel<<<gemm_grid, 128>>>(zc, 64, 64, 128, W1_r, b1_r, W2_r, b2_r);
    bn_apply_kernel<<<bn_grid, 256>>>(zc, 64, 128, 128, batch, pool, bn_gr, bn_br);  // copy z1->128

    // ---- layer 2: RED scatter (z1 @64 -> agg @128) + MLP in place @128 ----
    scatter_kernel<<<scat_grid, 256>>>(zc, 64, 128, ei);
    mlp2_kernel<<<gemm_grid, 128>>>(zc, 128, 128, 256,
                                    W1_r + (size_t)HH * HH, b1_r + HH,
                                    W2_r + (size_t)HH * HH, b2_r + HH);
    bn_apply_kernel<<<bn_grid, 256>>>(zc, 128, -1, 256, batch, pool, bn_gr + HH, bn_br + HH);

    (void)in_sizes; (void)n_in; (void)out_size;
}

// round 15
// speedup vs baseline: 1.2547x; 1.0152x over previous
#include <cuda_runtime.h>
#include <cuda_bf16.h>
#include <stdint.h>

// Problem constants
#define NN   50000
#define EE   800000
#define GG   512
#define DIN  128
#define HH   64
#define ZS   192              // L*H, row stride of z_cat and pool
#define BN_EPS 1e-5f

// scratch layout inside zc cols [128,192) viewed as int32 (free until bn_apply(L1))
#define SCR_A 0          // counts -> cursor, NN ints
#define SCR_B 51200      // offsets, NN+1 ints
#define SCR_P 102400     // scan partials, 196 ints
#define SCR_L 102656     // dst-sorted src list, EE ints (ends 902656 < 3.2M)
#define SCAN_NB 196      // ceil(NN/256)
#define GEMM_GRID 782    // ceil(NN/64)

typedef unsigned long long u64;

// ---------------- tiny device globals (~2 KB; device-code access only) ----------------
__device__ __align__(16) float g_stats[384];   // per layer: [0:64) sum, [64:128) sumsq
__device__ int g_is64;

// ---------------- helpers ----------------
__device__ __forceinline__ void red4(float* p, float4 v) {
    atomicAdd(reinterpret_cast<float4*>(p), v);
}

__device__ __forceinline__ long long ldidx(const void* p, long long i, int is64) {
    if (is64) return ((const long long*)p)[i];
    return (long long)((const int*)p)[i];
}

// strided scratch accessor: int slot i -> zc[(i/64)*192 + 128 + i%64]
__device__ __forceinline__ int* scr(float* zc, int i) {
    return reinterpret_cast<int*>(zc) + (long long)(i >> 6) * ZS + 128 + (i & 63);
}

// ---- packed f32x2 helpers (Blackwell FFMA2; PTX ISA 8.6 sm_100+) ----
__device__ __forceinline__ u64 pk2(float x) {
    u64 r; asm("mov.b64 %0, {%1, %1};" : "=l"(r) : "f"(x)); return r;
}
__device__ __forceinline__ void up2(u64 v, float& lo, float& hi) {
    asm("mov.b64 {%0, %1}, %2;" : "=f"(lo), "=f"(hi) : "l"(v));
}
__device__ __forceinline__ void fma2(u64& d, u64 a, u64 b) {
    asm("fma.rn.f32x2 %0, %1, %2, %0;" : "+l"(d) : "l"(a), "l"(b));
}

// ---------------- setup: zero pool + stats + counts, detect index dtype ----------------
__global__ void setup_kernel(float* zc, float* pool, const long long* ei) {
    int gt = blockIdx.x * 256 + threadIdx.x;
    for (int i = gt; i < GG * ZS; i += gridDim.x * 256) pool[i] = 0.0f;
    for (int i = gt; i < NN; i += gridDim.x * 256) *scr(zc, SCR_A + i) = 0;
    if (blockIdx.x == 0) {
        if (threadIdx.x < 128) {
            g_stats[threadIdx.x] = 0.0f;
            g_stats[threadIdx.x + 128] = 0.0f;
            g_stats[threadIdx.x + 256] = 0.0f;
        }
        if (threadIdx.x == 0) {
            int ok = 1;
            for (int i = 0; i < 16; i++) {
                long long v = ei[i];
                if (v < 0 || v >= NN) ok = 0;
            }
            g_is64 = ok;
        }
    }
}

// ======================= GEMM building blocks (FFMA2 core) =======================
// Block 128 threads, 64 nodes. Thread (ng=tid>>3, fg=tid&7) owns 4 nodes x 8 features,
// accumulated as 16 packed f32x2 (feature pairs).

__device__ __forceinline__ void stage_w(float* Ws, const float* __restrict__ W, int tid) {
    for (int i = tid; i < 1024; i += 128)
        reinterpret_cast<float4*>(Ws)[i] = reinterpret_cast<const float4*>(W)[i];
}

__device__ __forceinline__ void stage_x(float* Xs, const float* __restrict__ gx,
                                        int zstride, int node0, int tid) {
    int row = tid >> 1, part = tid & 1;
    int gn = node0 + row; if (gn >= NN) gn = NN - 1;
    const float4* src = reinterpret_cast<const float4*>(gx + (long long)gn * zstride);
    float4* dst = reinterpret_cast<float4*>(Xs + row * 68);
#pragma unroll
    for (int q = 0; q < 8; q++) dst[part * 8 + q] = src[part * 8 + q];
}

__device__ __forceinline__ void gemm_core2(const float* Xs, const float* Ws,
                                           int ng, int fg, u64* acc2) {
#pragma unroll
    for (int k4 = 0; k4 < 16; k4++) {
        float4 xv0 = *reinterpret_cast<const float4*>(Xs + (ng * 4 + 0) * 68 + k4 * 4);
        float4 xv1 = *reinterpret_cast<const float4*>(Xs + (ng * 4 + 1) * 68 + k4 * 4);
        float4 xv2 = *reinterpret_cast<const float4*>(Xs + (ng * 4 + 2) * 68 + k4 * 4);
        float4 xv3 = *reinterpret_cast<const float4*>(Xs + (ng * 4 + 3) * 68 + k4 * 4);
#pragma unroll
        for (int kk = 0; kk < 4; kk++) {
            const ulonglong2* wr = reinterpret_cast<const ulonglong2*>(
                Ws + (k4 * 4 + kk) * 64 + fg * 8);
            ulonglong2 wa = wr[0];
            ulonglong2 wb = wr[1];
            float v0 = (kk == 0) ? xv0.x : (kk == 1) ? xv0.y : (kk == 2) ? xv0.z : xv0.w;
            float v1 = (kk == 0) ? xv1.x : (kk == 1) ? xv1.y : (kk == 2) ? xv1.z : xv1.w;
            float v2 = (kk == 0) ? xv2.x : (kk == 1) ? xv2.y : (kk == 2) ? xv2.z : xv2.w;
            float v3 = (kk == 0) ? xv3.x : (kk == 1) ? xv3.y : (kk == 2) ? xv3.z : xv3.w;
            u64 x0 = pk2(v0), x1 = pk2(v1), x2 = pk2(v2), x3 = pk2(v3);
            fma2(acc2[0],  x0, wa.x); fma2(acc2[1],  x0, wa.y);
            fma2(acc2[2],  x0, wb.x); fma2(acc2[3],  x0, wb.y);
            fma2(acc2[4],  x1, wa.x); fma2(acc2[5],  x1, wa.y);
            fma2(acc2[6],  x1, wb.x); fma2(acc2[7],  x1, wb.y);
            fma2(acc2[8],  x2, wa.x); fma2(acc2[9],  x2, wa.y);
            fma2(acc2[10], x2, wb.x); fma2(acc2[11], x2, wb.y);
            fma2(acc2[12], x3, wa.x); fma2(acc2[13], x3, wa.y);
            fma2(acc2[14], x3, wb.x); fma2(acc2[15], x3, wb.y);
        }
    }
}

__device__ __forceinline__ void unpack_relu(const u64* acc2, float* o) {
#pragma unroll
    for (int i = 0; i < 4; i++) {
#pragma unroll
        for (int jp = 0; jp < 4; jp++) {
            float lo, hi;
            up2(acc2[i * 4 + jp], lo, hi);
            o[i * 8 + jp * 2]     = fmaxf(lo, 0.0f);
            o[i * 8 + jp * 2 + 1] = fmaxf(hi, 0.0f);
        }
    }
}

__device__ __forceinline__ void bias_init2(u64* acc2, const float* __restrict__ b, int fg) {
    const ulonglong2* bp = reinterpret_cast<const ulonglong2*>(b + fg * 8);
    ulonglong2 ba = bp[0], bb = bp[1];
#pragma unroll
    for (int i = 0; i < 4; i++) {
        acc2[i * 4 + 0] = ba.x; acc2[i * 4 + 1] = ba.y;
        acc2[i * 4 + 2] = bb.x; acc2[i * 4 + 3] = bb.y;
    }
}

__device__ __forceinline__ void store_o(float* zc, int node0, int col,
                                        int ng, int fg, const float* o) {
#pragma unroll
    for (int i = 0; i < 4; i++) {
        int node = node0 + ng * 4 + i;
        if (node < NN) {
            float* row = zc + (long long)node * ZS + col;
            *reinterpret_cast<float4*>(row + fg * 8) =
                make_float4(o[i*8+0], o[i*8+1], o[i*8+2], o[i*8+3]);
            *reinterpret_cast<float4*>(row + fg * 8 + 4) =
                make_float4(o[i*8+4], o[i*8+5], o[i*8+6], o[i*8+7]);
        }
    }
}

// per-block BN-stat partials into g_stats[stats_off..]; S >= 16*130 floats scratch.
__device__ __forceinline__ void stats_epi(float* S, const float* o, int stats_off,
                                          int ng, int fg, int node0, int tid) {
    float s[8], q[8];
#pragma unroll
    for (int j = 0; j < 8; j++) { s[j] = 0.0f; q[j] = 0.0f; }
#pragma unroll
    for (int i = 0; i < 4; i++) {
        if (node0 + ng * 4 + i < NN) {
#pragma unroll
            for (int j = 0; j < 8; j++) { float v = o[i*8+j]; s[j] += v; q[j] += v * v; }
        }
    }
#pragma unroll
    for (int j = 0; j < 8; j++) {
        S[ng * 130 + fg * 8 + j] = s[j];
        S[ng * 130 + 65 + fg * 8 + j] = q[j];
    }
    __syncthreads();
    int f = tid & 63, which = tid >> 6;
    float a = 0.0f;
#pragma unroll
    for (int g = 0; g < 16; g++) a += S[g * 130 + which * 65 + f];
    atomicAdd(&g_stats[stats_off + which * 64 + f], a);
}

// ---------------- merged: gemm1 (blocks < GEMM_GRID) || edge histogram (rest) -------------
// Independent work items sharing one launch: overlaps latency-bound atomics with GEMM.
__global__ void __launch_bounds__(128) gemm1_hist_kernel(
    const float* __restrict__ x, const float* __restrict__ W1, float* zc,
    const void* __restrict__ ei)
{
    __shared__ float Ws[4096];
    __shared__ float Xs[64 * 68];
    const int tid = threadIdx.x;

    if (blockIdx.x >= GEMM_GRID) {
        // histogram part: 8 edges per thread
        int base = ((blockIdx.x - GEMM_GRID) * 128 + tid) * 8;
        int is64 = g_is64;
#pragma unroll
        for (int j = 0; j < 8; j++) {
            int e = base + j;
            if (e < EE) {
                int d = (int)ldidx(ei, (long long)EE + e, is64);
                atomicAdd(scr(zc, SCR_A + d), 1);
            }
        }
        return;
    }

    const int fg = tid & 7, ng = tid >> 3;
    const int node0 = blockIdx.x * 64;

    u64 acc2[16];
#pragma unroll
    for (int q = 0; q < 16; q++) acc2[q] = 0ULL;

    for (int kc = 0; kc < 2; kc++) {
        __syncthreads();
        stage_w(Ws, W1 + kc * 64 * 64, tid);
        stage_x(Xs, x + kc * 64, DIN, node0, tid);
        __syncthreads();
        gemm_core2(Xs, Ws, ng, fg, acc2);
    }

    float o[32];
#pragma unroll
    for (int i = 0; i < 4; i++)
#pragma unroll
        for (int jp = 0; jp < 4; jp++)
            up2(acc2[i * 4 + jp], o[i * 8 + jp * 2], o[i * 8 + jp * 2 + 1]);
    store_o(zc, node0, 64, ng, fg, o);
}

// ---------------- scan (2 kernels; scan_apply folds in the top-level scan) ----------------
__device__ __forceinline__ int block_incl_scan(int* sh, int t, int v) {
    sh[t] = v;
    __syncthreads();
#pragma unroll
    for (int s = 1; s < 256; s <<= 1) {
        int add = (t >= s) ? sh[t - s] : 0;
        __syncthreads();
        sh[t] += add;
        __syncthreads();
    }
    return sh[t];
}

__global__ void scan_partials_kernel(float* zc) {
    __shared__ int sh[256];
    int t = threadIdx.x;
    int i = blockIdx.x * 256 + t;
    int c = (i < NN) ? *scr(zc, SCR_A + i) : 0;
    sh[t] = c;
    __syncthreads();
    for (int s = 128; s > 0; s >>= 1) {
        if (t < s) sh[t] += sh[t + s];
        __syncthreads();
    }
    if (t == 0) *scr(zc, SCR_P + blockIdx.x) = sh[0];
}

__global__ void scan_apply_kernel(float* zc) {
    __shared__ int sh[256];
    int t = threadIdx.x;
    // base = sum of partials of preceding blocks (each thread sums a strided subset)
    int pb = 0;
    for (int p = t; p < blockIdx.x; p += 256) pb += *scr(zc, SCR_P + p);
    sh[t] = pb;
    __syncthreads();
    for (int s = 128; s > 0; s >>= 1) {
        if (t < s) sh[t] += sh[t + s];
        __syncthreads();
    }
    int base = sh[0];
    __syncthreads();

    int i = blockIdx.x * 256 + t;
    int c = (i < NN) ? *scr(zc, SCR_A + i) : 0;
    int inc = block_incl_scan(sh, t, c);
    if (i < NN) {
        int off = base + inc - c;      // exclusive prefix
        *scr(zc, SCR_B + i) = off;     // offsets
        *scr(zc, SCR_A + i) = off;     // cursor init
    }
    if (blockIdx.x == SCAN_NB - 1 && t == 255) *scr(zc, SCR_B + NN) = EE;
}

__global__ void place_kernel(float* zc, const void* __restrict__ ei) {
    int base = (blockIdx.x * 256 + threadIdx.x) * 4;
    int is64 = g_is64;
#pragma unroll
    for (int j = 0; j < 4; j++) {
        int e = base + j;
        if (e < EE) {
            int s = (int)ldidx(ei, e, is64);
            int d = (int)ldidx(ei, (long long)EE + e, is64);
            int pos = atomicAdd(scr(zc, SCR_A + d), 1);
            *scr(zc, SCR_L + pos) = s;
        }
    }
}

// ---------------- gather: one warp per dst row; agg[n] = src[n] + sum src[list] ----------
__global__ void __launch_bounds__(256) gather_kernel(float* zc, int src_col, int agg_col) {
    int n = (blockIdx.x * 256 + threadIdx.x) >> 5;
    int lane = threadIdx.x & 31;
    if (n >= NN) return;
    const float* self = zc + (long long)n * ZS + src_col;
    float a0 = self[lane], a1 = self[lane + 32];
    int start = *scr(zc, SCR_B + n);
    int end   = *scr(zc, SCR_B + n + 1);
    float p0 = 0, p1 = 0, q0 = 0, q1 = 0, u0 = 0, u1 = 0, t0 = 0, t1 = 0;
    int e = start;
    for (; e + 3 < end; e += 4) {
        int s0 = *scr(zc, SCR_L + e);
        int s1 = *scr(zc, SCR_L + e + 1);
        int s2 = *scr(zc, SCR_L + e + 2);
        int s3 = *scr(zc, SCR_L + e + 3);
        const float* r0 = zc + (long long)s0 * ZS + src_col;
        const float* r1 = zc + (long long)s1 * ZS + src_col;
        const float* r2 = zc + (long long)s2 * ZS + src_col;
        const float* r3 = zc + (long long)s3 * ZS + src_col;
        p0 += r0[lane]; p1 += r0[lane + 32];
        q0 += r1[lane]; q1 += r1[lane + 32];
        u0 += r2[lane]; u1 += r2[lane + 32];
        t0 += r3[lane]; t1 += r3[lane + 32];
    }
    for (; e < end; e++) {
        int s0 = *scr(zc, SCR_L + e);
        const float* r0 = zc + (long long)s0 * ZS + src_col;
        p0 += r0[lane]; p1 += r0[lane + 32];
    }
    a0 += (p0 + q0) + (u0 + t0);
    a1 += (p1 + q1) + (u1 + t1);
    float* out = zc + (long long)n * ZS + agg_col;
    out[lane] = a0;
    out[lane + 32] = a1;
}

// ---------------- L0 MLP tail: h = relu( relu(agg+b1) @ W2 + b2 ), in place + stats ------
__global__ void __launch_bounds__(128) mlp0_kernel(
    float* zc, int col, int stats_off,
    const float* __restrict__ W2, const float* __restrict__ b1,
    const float* __restrict__ b2)
{
    __shared__ float Ws[4096];
    __shared__ float Xs[64 * 68];
    const int tid = threadIdx.x, fg = tid & 7, ng = tid >> 3;
    const int node0 = blockIdx.x * 64;

    stage_w(Ws, W2, tid);
    {   // Xs = relu(agg + b1)
        int row = tid >> 1, part = tid & 1;
        int gn = node0 + row; if (gn >= NN) gn = NN - 1;
        const float4* src = reinterpret_cast<const float4*>(zc + (long long)gn * ZS + col);
        float4* dst = reinterpret_cast<float4*>(Xs + row * 68);
#pragma unroll
        for (int q = 0; q < 8; q++) {
            int c4 = part * 8 + q;
            float4 a = src[c4];
            float4 bb = reinterpret_cast<const float4*>(b1)[c4];
            dst[c4] = make_float4(fmaxf(a.x + bb.x, 0.0f), fmaxf(a.y + bb.y, 0.0f),
                                  fmaxf(a.z + bb.z, 0.0f), fmaxf(a.w + bb.w, 0.0f));
        }
    }
    __syncthreads();

    u64 acc2[16];
    bias_init2(acc2, b2, fg);
    gemm_core2(Xs, Ws, ng, fg, acc2);

    float o[32];
    unpack_relu(acc2, o);
    store_o(zc, node0, col, ng, fg, o);
    __syncthreads();
    stats_epi(Ws, o, stats_off, ng, fg, node0, tid);
}

// ---------------- L1/L2 MLP: h = relu( relu(agg@W1+b1) @ W2 + b2 ) + stats ----------------
__global__ void __launch_bounds__(128) mlp2_kernel(
    float* zc, int in_col, int out_col, int stats_off,
    const float* __restrict__ W1, const float* __restrict__ b1,
    const float* __restrict__ W2, const float* __restrict__ b2)
{
    __shared__ float Ws[4096];
    __shared__ float Xs[64 * 68];
    const int tid = threadIdx.x, fg = tid & 7, ng = tid >> 3;
    const int node0 = blockIdx.x * 64;

    stage_w(Ws, W1, tid);
    stage_x(Xs, zc + in_col, ZS, node0, tid);
    __syncthreads();

    u64 acc2[16];
#pragma unroll
    for (int q = 0; q < 16; q++) acc2[q] = 0ULL;
    gemm_core2(Xs, Ws, ng, fg, acc2);
    __syncthreads();

    {
        const ulonglong2* bp = reinterpret_cast<const ulonglong2*>(b1 + fg * 8);
        ulonglong2 ca = bp[0], cb = bp[1];
        u64 bb4[4] = {ca.x, ca.y, cb.x, cb.y};
#pragma unroll
        for (int i = 0; i < 4; i++) {
#pragma unroll
            for (int jp = 0; jp < 4; jp++) {
                float lo, hi, blo, bhi;
                up2(acc2[i * 4 + jp], lo, hi);
                up2(bb4[jp], blo, bhi);
                lo = fmaxf(lo + blo, 0.0f);
                hi = fmaxf(hi + bhi, 0.0f);
                *reinterpret_cast<float2*>(Xs + (ng * 4 + i) * 68 + fg * 8 + jp * 2) =
                    make_float2(lo, hi);
            }
        }
    }
    stage_w(Ws, W2, tid);
    __syncthreads();

    bias_init2(acc2, b2, fg);
    gemm_core2(Xs, Ws, ng, fg, acc2);

    float o[32];
    unpack_relu(acc2, o);
    store_o(zc, node0, out_col, ng, fg, o);
    __syncthreads();
    stats_epi(Ws, o, stats_off, ng, fg, node0, tid);
}

// ---------------- L2 RED scatter (agg col init'd with z1 copy by bn_apply) ----------------
__global__ void scatter_kernel(float* zc, int src_col, int agg_col,
                               const void* __restrict__ ei) {
    int gtid = blockIdx.x * 256 + threadIdx.x;
    int e = gtid >> 3;
    int c = gtid & 7;
    if (e >= EE) return;
    int is64 = g_is64;
    long long s = ldidx(ei, e, is64);
    long long d = ldidx(ei, (long long)EE + e, is64);
    const float4* sp = reinterpret_cast<const float4*>(zc + s * ZS + src_col);
    float4 v0 = sp[c];
    float4 v1 = sp[c + 8];
    float* dp = zc + d * ZS + agg_col;
    red4(dp + c * 4, v0);
    red4(dp + 32 + c * 4, v1);
}

// ---------------- BN apply: finalize (per block, from stats) + normalize + pool + copy ----
__global__ void bn_apply_kernel(float* zc, int col_off, int copy_off, int stats_off,
                                const void* __restrict__ batch,
                                float* __restrict__ pool,
                                const float* __restrict__ gam,
                                const float* __restrict__ bet)
{
    __shared__ __align__(16) float sc_s[64], sh_s[64];
    int t = threadIdx.x;
    if (t < 64) {
        float mean = g_stats[stats_off + t] * (1.0f / NN);
        float var = g_stats[stats_off + 64 + t] * (1.0f / NN) - mean * mean;
        var = fmaxf(var, 0.0f);
        float s = gam[t] * rsqrtf(var + BN_EPS);
        sc_s[t] = s;
        sh_s[t] = bet[t] - mean * s;
    }
    __syncthreads();

    int gt = blockIdx.x * 256 + t;
    int n = gt >> 4;
    int c = gt & 15;
    if (n >= NN) return;
    int is64 = g_is64;
    float* row = zc + (long long)n * ZS;
    float4 h4 = *reinterpret_cast<float4*>(row + col_off + c * 4);
    float4 sc = *reinterpret_cast<const float4*>(sc_s + c * 4);
    float4 sh = *reinterpret_cast<const float4*>(sh_s + c * 4);
    float4 z;
    z.x = h4.x * sc.x + sh.x;
    z.y = h4.y * sc.y + sh.y;
    z.z = h4.z * sc.z + sh.z;
    z.w = h4.w * sc.w + sh.w;
    *reinterpret_cast<float4*>(row + col_off + c * 4) = z;
    if (copy_off >= 0)
        *reinterpret_cast<float4*>(row + copy_off + c * 4) = z;
    long long b = ldidx(batch, n, is64);
    red4(pool + b * ZS + col_off + c * 4, z);
}

// ---------------- launch ----------------
extern "C" void kernel_launch(void* const* d_in, const int* in_sizes, int n_in,
                              void* d_out, int out_size)
{
    const float* x     = (const float*)d_in[0];
    const void*  ei    = d_in[1];
    const void*  batch = d_in[2];
    const float* W1_0  = (const float*)d_in[3];
    const float* b1_0  = (const float*)d_in[4];
    const float* W2_0  = (const float*)d_in[5];
    const float* b2_0  = (const float*)d_in[6];
    const float* bn_g0 = (const float*)d_in[7];
    const float* bn_b0 = (const float*)d_in[8];
    const float* W1_r  = (const float*)d_in[9];
    const float* b1_r  = (const float*)d_in[10];
    const float* W2_r  = (const float*)d_in[11];
    const float* b2_r  = (const float*)d_in[12];
    const float* bn_gr = (const float*)d_in[13];
    const float* bn_br = (const float*)d_in[14];

    float* zc   = (float*)d_out;
    float* pool = zc + (long long)NN * ZS;

    const int edge4_grid = (EE + 1023) / 1024;       // 782 (4 edges/thread, place)
    const int gath_grid = (NN * 32 + 255) / 256;     // 6250
    const int scat_grid = (EE * 8) / 256;            // 25000
    const int bn_grid   = (NN * 16 + 255) / 256;     // 3125

    // setup, then merged gemm1 || histogram (independent work, one launch)
    setup_kernel<<<256, 256>>>(zc, pool, (const long long*)ei);
    gemm1_hist_kernel<<<GEMM_GRID * 2, 128>>>(x, W1_0, zc, ei);
    scan_partials_kernel<<<SCAN_NB, 256>>>(zc);
    scan_apply_kernel<<<SCAN_NB, 256>>>(zc);
    place_kernel<<<edge4_grid, 256>>>(zc, ei);

    // ---- layer 0: gather y0 (col 64) -> agg @ col 0; MLP in place @ 0 ----
    gather_kernel<<<gath_grid, 256>>>(zc, 64, 0);
    mlp0_kernel<<<GEMM_GRID, 128>>>(zc, 0, 0, W2_0, b1_0, b2_0);
    bn_apply_kernel<<<bn_grid, 256>>>(zc, 0, -1, 0, batch, pool, bn_g0, bn_b0);

    // ---- layer 1: gather z0 (col 0) -> agg @ col 64; MLP in place @ 64 ----
    gather_kernel<<<gath_grid, 256>>>(zc, 0, 64);
    mlp2_kernel<<<GEMM_GRID, 128>>>(zc, 64, 64, 128, W1_r, b1_r, W2_r, b2_r);
    bn_apply_kernel<<<bn_grid, 256>>>(zc, 64, 128, 128, batch, pool, bn_gr, bn_br);  // copy z1->128

    // ---- layer 2: RED scatter (z1 @64 -> agg @128) + MLP in place @128 ----
    scatter_kernel<<<scat_grid, 256>>>(zc, 64, 128, ei);
    mlp2_kernel<<<GEMM_GRID, 128>>>(zc, 128, 128, 256,
                                    W1_r + (size_t)HH * HH, b1_r + HH,
                                    W2_r + (size_t)HH * HH, b2_r + HH);
    bn_apply_kernel<<<bn_grid, 256>>>(zc, 128, -1, 256, batch, pool, bn_gr + HH, bn_br + HH);

    (void)in_sizes; (void)n_in; (void)out_size;
}

// round 17
// speedup vs baseline: 1.2701x; 1.0123x over previous
#include <cuda_runtime.h>
#include <cuda_bf16.h>
#include <stdint.h>

// Problem constants
#define NN   50000
#define EE   800000
#define GG   512
#define DIN  128
#define HH   64
#define ZS   192              // L*H, row stride of z_cat and pool
#define BN_EPS 1e-5f

// scratch layout inside zc cols [128,192) viewed as int32 (free until bn_apply(L1))
#define SCR_A 0          // counts -> cursor, NN ints
#define SCR_B 51200      // offsets, NN+1 ints
#define SCR_P 102400     // scan partials (lookback; -1 = not ready), 196 ints
#define SCR_L 102656     // dst-sorted src list, EE ints (ends 902656 < 3.2M)
#define SCAN_NB 196      // ceil(NN/256)
#define GEMM_GRID 782    // ceil(NN/64)

typedef unsigned long long u64;

// ---------------- tiny device globals (~2 KB; device-code access only) ----------------
__device__ __align__(16) float g_stats[384];   // per layer: [0:64) sum, [64:128) sumsq
__device__ int g_is64;

// ---------------- helpers ----------------
__device__ __forceinline__ void red4(float* p, float4 v) {
    atomicAdd(reinterpret_cast<float4*>(p), v);
}

__device__ __forceinline__ long long ldidx(const void* p, long long i, int is64) {
    if (is64) return ((const long long*)p)[i];
    return (long long)((const int*)p)[i];
}

// strided scratch accessor: int slot i -> zc[(i/64)*192 + 128 + i%64]
__device__ __forceinline__ int* scr(float* zc, int i) {
    return reinterpret_cast<int*>(zc) + (long long)(i >> 6) * ZS + 128 + (i & 63);
}

// ---- packed f32x2 helpers (Blackwell FFMA2; PTX ISA 8.6 sm_100+) ----
__device__ __forceinline__ u64 pk2(float x) {
    u64 r; asm("mov.b64 %0, {%1, %1};" : "=l"(r) : "f"(x)); return r;
}
__device__ __forceinline__ void up2(u64 v, float& lo, float& hi) {
    asm("mov.b64 {%0, %1}, %2;" : "=f"(lo), "=f"(hi) : "l"(v));
}
__device__ __forceinline__ void fma2(u64& d, u64 a, u64 b) {
    asm("fma.rn.f32x2 %0, %1, %2, %0;" : "+l"(d) : "l"(a), "l"(b));
}

// ---------------- setup: zero pool + stats + counts + lookback flags, detect dtype --------
__global__ void setup_kernel(float* zc, float* pool, const long long* ei) {
    int gt = blockIdx.x * 256 + threadIdx.x;
    for (int i = gt; i < GG * ZS; i += gridDim.x * 256) pool[i] = 0.0f;
    for (int i = gt; i < NN; i += gridDim.x * 256) *scr(zc, SCR_A + i) = 0;
    if (gt < SCAN_NB) *scr(zc, SCR_P + gt) = -1;   // lookback sentinel
    if (blockIdx.x == 0) {
        if (threadIdx.x < 128) {
            g_stats[threadIdx.x] = 0.0f;
            g_stats[threadIdx.x + 128] = 0.0f;
            g_stats[threadIdx.x + 256] = 0.0f;
        }
        if (threadIdx.x == 0) {
            int ok = 1;
            for (int i = 0; i < 16; i++) {
                long long v = ei[i];
                if (v < 0 || v >= NN) ok = 0;
            }
            g_is64 = ok;
        }
    }
}

// ======================= GEMM building blocks (FFMA2 core) =======================
// Block 128 threads, 64 nodes. Thread (ng=tid>>3, fg=tid&7) owns 4 nodes x 8 features,
// accumulated as 16 packed f32x2 (feature pairs).

__device__ __forceinline__ void stage_w(float* Ws, const float* __restrict__ W, int tid) {
    for (int i = tid; i < 1024; i += 128)
        reinterpret_cast<float4*>(Ws)[i] = reinterpret_cast<const float4*>(W)[i];
}

__device__ __forceinline__ void stage_x(float* Xs, const float* __restrict__ gx,
                                        int zstride, int node0, int tid) {
    int row = tid >> 1, part = tid & 1;
    int gn = node0 + row; if (gn >= NN) gn = NN - 1;
    const float4* src = reinterpret_cast<const float4*>(gx + (long long)gn * zstride);
    float4* dst = reinterpret_cast<float4*>(Xs + row * 68);
#pragma unroll
    for (int q = 0; q < 8; q++) dst[part * 8 + q] = src[part * 8 + q];
}

__device__ __forceinline__ void gemm_core2(const float* Xs, const float* Ws,
                                           int ng, int fg, u64* acc2) {
#pragma unroll
    for (int k4 = 0; k4 < 16; k4++) {
        float4 xv0 = *reinterpret_cast<const float4*>(Xs + (ng * 4 + 0) * 68 + k4 * 4);
        float4 xv1 = *reinterpret_cast<const float4*>(Xs + (ng * 4 + 1) * 68 + k4 * 4);
        float4 xv2 = *reinterpret_cast<const float4*>(Xs + (ng * 4 + 2) * 68 + k4 * 4);
        float4 xv3 = *reinterpret_cast<const float4*>(Xs + (ng * 4 + 3) * 68 + k4 * 4);
#pragma unroll
        for (int kk = 0; kk < 4; kk++) {
            const ulonglong2* wr = reinterpret_cast<const ulonglong2*>(
                Ws + (k4 * 4 + kk) * 64 + fg * 8);
            ulonglong2 wa = wr[0];
            ulonglong2 wb = wr[1];
            float v0 = (kk == 0) ? xv0.x : (kk == 1) ? xv0.y : (kk == 2) ? xv0.z : xv0.w;
            float v1 = (kk == 0) ? xv1.x : (kk == 1) ? xv1.y : (kk == 2) ? xv1.z : xv1.w;
            float v2 = (kk == 0) ? xv2.x : (kk == 1) ? xv2.y : (kk == 2) ? xv2.z : xv2.w;
            float v3 = (kk == 0) ? xv3.x : (kk == 1) ? xv3.y : (kk == 2) ? xv3.z : xv3.w;
            u64 x0 = pk2(v0), x1 = pk2(v1), x2 = pk2(v2), x3 = pk2(v3);
            fma2(acc2[0],  x0, wa.x); fma2(acc2[1],  x0, wa.y);
            fma2(acc2[2],  x0, wb.x); fma2(acc2[3],  x0, wb.y);
            fma2(acc2[4],  x1, wa.x); fma2(acc2[5],  x1, wa.y);
            fma2(acc2[6],  x1, wb.x); fma2(acc2[7],  x1, wb.y);
            fma2(acc2[8],  x2, wa.x); fma2(acc2[9],  x2, wa.y);
            fma2(acc2[10], x2, wb.x); fma2(acc2[11], x2, wb.y);
            fma2(acc2[12], x3, wa.x); fma2(acc2[13], x3, wa.y);
            fma2(acc2[14], x3, wb.x); fma2(acc2[15], x3, wb.y);
        }
    }
}

__device__ __forceinline__ void unpack_relu(const u64* acc2, float* o) {
#pragma unroll
    for (int i = 0; i < 4; i++) {
#pragma unroll
        for (int jp = 0; jp < 4; jp++) {
            float lo, hi;
            up2(acc2[i * 4 + jp], lo, hi);
            o[i * 8 + jp * 2]     = fmaxf(lo, 0.0f);
            o[i * 8 + jp * 2 + 1] = fmaxf(hi, 0.0f);
        }
    }
}

__device__ __forceinline__ void bias_init2(u64* acc2, const float* __restrict__ b, int fg) {
    const ulonglong2* bp = reinterpret_cast<const ulonglong2*>(b + fg * 8);
    ulonglong2 ba = bp[0], bb = bp[1];
#pragma unroll
    for (int i = 0; i < 4; i++) {
        acc2[i * 4 + 0] = ba.x; acc2[i * 4 + 1] = ba.y;
        acc2[i * 4 + 2] = bb.x; acc2[i * 4 + 3] = bb.y;
    }
}

__device__ __forceinline__ void store_o(float* zc, int node0, int col,
                                        int ng, int fg, const float* o) {
#pragma unroll
    for (int i = 0; i < 4; i++) {
        int node = node0 + ng * 4 + i;
        if (node < NN) {
            float* row = zc + (long long)node * ZS + col;
            *reinterpret_cast<float4*>(row + fg * 8) =
                make_float4(o[i*8+0], o[i*8+1], o[i*8+2], o[i*8+3]);
            *reinterpret_cast<float4*>(row + fg * 8 + 4) =
                make_float4(o[i*8+4], o[i*8+5], o[i*8+6], o[i*8+7]);
        }
    }
}

// per-block BN-stat partials into g_stats[stats_off..]; S >= 16*130 floats scratch.
__device__ __forceinline__ void stats_epi(float* S, const float* o, int stats_off,
                                          int ng, int fg, int node0, int tid) {
    float s[8], q[8];
#pragma unroll
    for (int j = 0; j < 8; j++) { s[j] = 0.0f; q[j] = 0.0f; }
#pragma unroll
    for (int i = 0; i < 4; i++) {
        if (node0 + ng * 4 + i < NN) {
#pragma unroll
            for (int j = 0; j < 8; j++) { float v = o[i*8+j]; s[j] += v; q[j] += v * v; }
        }
    }
#pragma unroll
    for (int j = 0; j < 8; j++) {
        S[ng * 130 + fg * 8 + j] = s[j];
        S[ng * 130 + 65 + fg * 8 + j] = q[j];
    }
    __syncthreads();
    int f = tid & 63, which = tid >> 6;
    float a = 0.0f;
#pragma unroll
    for (int g = 0; g < 16; g++) a += S[g * 130 + which * 65 + f];
    atomicAdd(&g_stats[stats_off + which * 64 + f], a);
}

// ---------------- merged: gemm1 (blocks < GEMM_GRID) || edge histogram (rest) -------------
__global__ void __launch_bounds__(128) gemm1_hist_kernel(
    const float* __restrict__ x, const float* __restrict__ W1, float* zc,
    const void* __restrict__ ei)
{
    __shared__ float Ws[4096];
    __shared__ float Xs[64 * 68];
    const int tid = threadIdx.x;

    if (blockIdx.x >= GEMM_GRID) {
        int base = ((blockIdx.x - GEMM_GRID) * 128 + tid) * 8;
        int is64 = g_is64;
#pragma unroll
        for (int j = 0; j < 8; j++) {
            int e = base + j;
            if (e < EE) {
                int d = (int)ldidx(ei, (long long)EE + e, is64);
                atomicAdd(scr(zc, SCR_A + d), 1);
            }
        }
        return;
    }

    const int fg = tid & 7, ng = tid >> 3;
    const int node0 = blockIdx.x * 64;

    u64 acc2[16];
#pragma unroll
    for (int q = 0; q < 16; q++) acc2[q] = 0ULL;

    for (int kc = 0; kc < 2; kc++) {
        __syncthreads();
        stage_w(Ws, W1 + kc * 64 * 64, tid);
        stage_x(Xs, x + kc * 64, DIN, node0, tid);
        __syncthreads();
        gemm_core2(Xs, Ws, ng, fg, acc2);
    }

    float o[32];
#pragma unroll
    for (int i = 0; i < 4; i++)
#pragma unroll
        for (int jp = 0; jp < 4; jp++)
            up2(acc2[i * 4 + jp], o[i * 8 + jp * 2], o[i * 8 + jp * 2 + 1]);
    store_o(zc, node0, 64, ng, fg, o);
}

// ---------------- single-pass decoupled-lookback scan ----------------
// All SCAN_NB=196 blocks are simultaneously resident (<< 148 SMs x 8), so the
// spin on predecessors' partials cannot livelock. Partial word doubles as flag
// (-1 = not ready; counts are >= 0).
__global__ void __launch_bounds__(256) scan_lookback_kernel(float* zc) {
    __shared__ int sh[256];
    int t = threadIdx.x;
    int b = blockIdx.x;
    int i = b * 256 + t;
    int c = (i < NN) ? *scr(zc, SCR_A + i) : 0;

    // block aggregate -> publish
    sh[t] = c;
    __syncthreads();
    for (int s = 128; s > 0; s >>= 1) {
        if (t < s) sh[t] += sh[t + s];
        __syncthreads();
    }
    if (t == 0) atomicExch(scr(zc, SCR_P + b), sh[0]);   // single-word value+flag
    __syncthreads();

    // lookback: sum predecessors' partials (spin until published)
    int pb = 0;
    for (int p = t; p < b; p += 256) {
        int v;
        do { v = atomicAdd(scr(zc, SCR_P + p), 0); } while (v < 0);
        pb += v;
    }
    sh[t] = pb;
    __syncthreads();
    for (int s = 128; s > 0; s >>= 1) {
        if (t < s) sh[t] += sh[t + s];
        __syncthreads();
    }
    int base = sh[0];
    __syncthreads();

    // block-local inclusive scan of counts
    sh[t] = c;
    __syncthreads();
#pragma unroll
    for (int s = 1; s < 256; s <<= 1) {
        int add = (t >= s) ? sh[t - s] : 0;
        __syncthreads();
        sh[t] += add;
        __syncthreads();
    }
    if (i < NN) {
        int off = base + sh[t] - c;    // exclusive prefix
        *scr(zc, SCR_B + i) = off;     // offsets
        *scr(zc, SCR_A + i) = off;     // cursor init
    }
    if (b == SCAN_NB - 1 && t == 255) *scr(zc, SCR_B + NN) = EE;
}

__global__ void place_kernel(float* zc, const void* __restrict__ ei) {
    int base = (blockIdx.x * 256 + threadIdx.x) * 4;
    int is64 = g_is64;
#pragma unroll
    for (int j = 0; j < 4; j++) {
        int e = base + j;
        if (e < EE) {
            int s = (int)ldidx(ei, e, is64);
            int d = (int)ldidx(ei, (long long)EE + e, is64);
            int pos = atomicAdd(scr(zc, SCR_A + d), 1);
            *scr(zc, SCR_L + pos) = s;
        }
    }
}

// ---------------- gather: one warp per dst row; agg[n] = src[n] + sum src[list] ----------
__global__ void __launch_bounds__(256) gather_kernel(float* zc, int src_col, int agg_col) {
    int n = (blockIdx.x * 256 + threadIdx.x) >> 5;
    int lane = threadIdx.x & 31;
    if (n >= NN) return;
    const float* self = zc + (long long)n * ZS + src_col;
    float a0 = self[lane], a1 = self[lane + 32];
    int start = *scr(zc, SCR_B + n);
    int end   = *scr(zc, SCR_B + n + 1);
    float p0 = 0, p1 = 0, q0 = 0, q1 = 0, u0 = 0, u1 = 0, t0 = 0, t1 = 0;
    int e = start;
    for (; e + 3 < end; e += 4) {
        int s0 = *scr(zc, SCR_L + e);
        int s1 = *scr(zc, SCR_L + e + 1);
        int s2 = *scr(zc, SCR_L + e + 2);
        int s3 = *scr(zc, SCR_L + e + 3);
        const float* r0 = zc + (long long)s0 * ZS + src_col;
        const float* r1 = zc + (long long)s1 * ZS + src_col;
        const float* r2 = zc + (long long)s2 * ZS + src_col;
        const float* r3 = zc + (long long)s3 * ZS + src_col;
        p0 += r0[lane]; p1 += r0[lane + 32];
        q0 += r1[lane]; q1 += r1[lane + 32];
        u0 += r2[lane]; u1 += r2[lane + 32];
        t0 += r3[lane]; t1 += r3[lane + 32];
    }
    for (; e < end; e++) {
        int s0 = *scr(zc, SCR_L + e);
        const float* r0 = zc + (long long)s0 * ZS + src_col;
        p0 += r0[lane]; p1 += r0[lane + 32];
    }
    a0 += (p0 + q0) + (u0 + t0);
    a1 += (p1 + q1) + (u1 + t1);
    float* out = zc + (long long)n * ZS + agg_col;
    out[lane] = a0;
    out[lane + 32] = a1;
}

// ---------------- L0 MLP tail: h = relu( relu(agg+b1) @ W2 + b2 ), in place + stats ------
__global__ void __launch_bounds__(128) mlp0_kernel(
    float* zc, int col, int stats_off,
    const float* __restrict__ W2, const float* __restrict__ b1,
    const float* __restrict__ b2)
{
    __shared__ float Ws[4096];
    __shared__ float Xs[64 * 68];
    const int tid = threadIdx.x, fg = tid & 7, ng = tid >> 3;
    const int node0 = blockIdx.x * 64;

    stage_w(Ws, W2, tid);
    {   // Xs = relu(agg + b1)
        int row = tid >> 1, part = tid & 1;
        int gn = node0 + row; if (gn >= NN) gn = NN - 1;
        const float4* src = reinterpret_cast<const float4*>(zc + (long long)gn * ZS + col);
        float4* dst = reinterpret_cast<float4*>(Xs + row * 68);
#pragma unroll
        for (int q = 0; q < 8; q++) {
            int c4 = part * 8 + q;
            float4 a = src[c4];
            float4 bb = reinterpret_cast<const float4*>(b1)[c4];
            dst[c4] = make_float4(fmaxf(a.x + bb.x, 0.0f), fmaxf(a.y + bb.y, 0.0f),
                                  fmaxf(a.z + bb.z, 0.0f), fmaxf(a.w + bb.w, 0.0f));
        }
    }
    __syncthreads();

    u64 acc2[16];
    bias_init2(acc2, b2, fg);
    gemm_core2(Xs, Ws, ng, fg, acc2);

    float o[32];
    unpack_relu(acc2, o);
    store_o(zc, node0, col, ng, fg, o);
    __syncthreads();
    stats_epi(Ws, o, stats_off, ng, fg, node0, tid);
}

// ---------------- L1/L2 MLP: h = relu( relu(agg@W1+b1) @ W2 + b2 ) + stats ----------------
__global__ void __launch_bounds__(128) mlp2_kernel(
    float* zc, int in_col, int out_col, int stats_off,
    const float* __restrict__ W1, const float* __restrict__ b1,
    const float* __restrict__ W2, const float* __restrict__ b2)
{
    __shared__ float Ws[4096];
    __shared__ float Xs[64 * 68];
    const int tid = threadIdx.x, fg = tid & 7, ng = tid >> 3;
    const int node0 = blockIdx.x * 64;

    stage_w(Ws, W1, tid);
    stage_x(Xs, zc + in_col, ZS, node0, tid);
    __syncthreads();

    u64 acc2[16];
#pragma unroll
    for (int q = 0; q < 16; q++) acc2[q] = 0ULL;
    gemm_core2(Xs, Ws, ng, fg, acc2);
    __syncthreads();

    {
        const ulonglong2* bp = reinterpret_cast<const ulonglong2*>(b1 + fg * 8);
        ulonglong2 ca = bp[0], cb = bp[1];
        u64 bb4[4] = {ca.x, ca.y, cb.x, cb.y};
#pragma unroll
        for (int i = 0; i < 4; i++) {
#pragma unroll
            for (int jp = 0; jp < 4; jp++) {
                float lo, hi, blo, bhi;
                up2(acc2[i * 4 + jp], lo, hi);
                up2(bb4[jp], blo, bhi);
                lo = fmaxf(lo + blo, 0.0f);
                hi = fmaxf(hi + bhi, 0.0f);
                *reinterpret_cast<float2*>(Xs + (ng * 4 + i) * 68 + fg * 8 + jp * 2) =
                    make_float2(lo, hi);
            }
        }
    }
    stage_w(Ws, W2, tid);
    __syncthreads();

    bias_init2(acc2, b2, fg);
    gemm_core2(Xs, Ws, ng, fg, acc2);

    float o[32];
    unpack_relu(acc2, o);
    store_o(zc, node0, out_col, ng, fg, o);
    __syncthreads();
    stats_epi(Ws, o, stats_off, ng, fg, node0, tid);
}

// ---------------- L2 RED scatter (agg col init'd with z1 copy by bn_apply) ----------------
__global__ void scatter_kernel(float* zc, int src_col, int agg_col,
                               const void* __restrict__ ei) {
    int gtid = blockIdx.x * 256 + threadIdx.x;
    int e = gtid >> 3;
    int c = gtid & 7;
    if (e >= EE) return;
    int is64 = g_is64;
    long long s = ldidx(ei, e, is64);
    long long d = ldidx(ei, (long long)EE + e, is64);
    const float4* sp = reinterpret_cast<const float4*>(zc + s * ZS + src_col);
    float4 v0 = sp[c];
    float4 v1 = sp[c + 8];
    float* dp = zc + d * ZS + agg_col;
    red4(dp + c * 4, v0);
    red4(dp + 32 + c * 4, v1);
}

// ---------------- BN apply: finalize (per block, from stats) + normalize + pool + copy ----
__global__ void bn_apply_kernel(float* zc, int col_off, int copy_off, int stats_off,
                                const void* __restrict__ batch,
                                float* __restrict__ pool,
                                const float* __restrict__ gam,
                                const float* __restrict__ bet)
{
    __shared__ __align__(16) float sc_s[64], sh_s[64];
    int t = threadIdx.x;
    if (t < 64) {
        float mean = g_stats[stats_off + t] * (1.0f / NN);
        float var = g_stats[stats_off + 64 + t] * (1.0f / NN) - mean * mean;
        var = fmaxf(var, 0.0f);
        float s = gam[t] * rsqrtf(var + BN_EPS);
        sc_s[t] = s;
        sh_s[t] = bet[t] - mean * s;
    }
    __syncthreads();

    int gt = blockIdx.x * 256 + t;
    int n = gt >> 4;
    int c = gt & 15;
    if (n >= NN) return;
    int is64 = g_is64;
    float* row = zc + (long long)n * ZS;
    float4 h4 = *reinterpret_cast<float4*>(row + col_off + c * 4);
    float4 sc = *reinterpret_cast<const float4*>(sc_s + c * 4);
    float4 sh = *reinterpret_cast<const float4*>(sh_s + c * 4);
    float4 z;
    z.x = h4.x * sc.x + sh.x;
    z.y = h4.y * sc.y + sh.y;
    z.z = h4.z * sc.z + sh.z;
    z.w = h4.w * sc.w + sh.w;
    *reinterpret_cast<float4*>(row + col_off + c * 4) = z;
    if (copy_off >= 0)
        *reinterpret_cast<float4*>(row + copy_off + c * 4) = z;
    long long b = ldidx(batch, n, is64);
    red4(pool + b * ZS + col_off + c * 4, z);
}

// ---------------- launch ----------------
extern "C" void kernel_launch(void* const* d_in, const int* in_sizes, int n_in,
                              void* d_out, int out_size)
{
    const float* x     = (const float*)d_in[0];
    const void*  ei    = d_in[1];
    const void*  batch = d_in[2];
    const float* W1_0  = (const float*)d_in[3];
    const float* b1_0  = (const float*)d_in[4];
    const float* W2_0  = (const float*)d_in[5];
    const float* b2_0  = (const float*)d_in[6];
    const float* bn_g0 = (const float*)d_in[7];
    const float* bn_b0 = (const float*)d_in[8];
    const float* W1_r  = (const float*)d_in[9];
    const float* b1_r  = (const float*)d_in[10];
    const float* W2_r  = (const float*)d_in[11];
    const float* b2_r  = (const float*)d_in[12];
    const float* bn_gr = (const float*)d_in[13];
    const float* bn_br = (const float*)d_in[14];

    float* zc   = (float*)d_out;
    float* pool = zc + (long long)NN * ZS;

    const int edge4_grid = (EE + 1023) / 1024;       // 782 (4 edges/thread, place)
    const int gath_grid = (NN * 32 + 255) / 256;     // 6250
    const int scat_grid = (EE * 8) / 256;            // 25000
    const int bn_grid   = (NN * 16 + 255) / 256;     // 3125

    // setup, merged gemm1 || histogram, single-pass scan, place
    setup_kernel<<<256, 256>>>(zc, pool, (const long long*)ei);
    gemm1_hist_kernel<<<GEMM_GRID * 2, 128>>>(x, W1_0, zc, ei);
    scan_lookback_kernel<<<SCAN_NB, 256>>>(zc);
    place_kernel<<<edge4_grid, 256>>>(zc, ei);

    // ---- layer 0: gather y0 (col 64) -> agg @ col 0; MLP in place @ 0 ----
    gather_kernel<<<gath_grid, 256>>>(zc, 64, 0);
    mlp0_kernel<<<GEMM_GRID, 128>>>(zc, 0, 0, W2_0, b1_0, b2_0);
    bn_apply_kernel<<<bn_grid, 256>>>(zc, 0, -1, 0, batch, pool, bn_g0, bn_b0);

    // ---- layer 1: gather z0 (col 0) -> agg @ col 64; MLP in place @ 64 ----
    gather_kernel<<<gath_grid, 256>>>(zc, 0, 64);
    mlp2_kernel<<<GEMM_GRID, 128>>>(zc, 64, 64, 128, W1_r, b1_r, W2_r, b2_r);
    bn_apply_kernel<<<bn_grid, 256>>>(zc, 64, 128, 128, batch, pool, bn_gr, bn_br);  // copy z1->128

    // ---- layer 2: RED scatter (z1 @64 -> agg @128) + MLP in place @128 ----
    scatter_kernel<<<scat_grid, 256>>>(zc, 64, 128, ei);
    mlp2_kernel<<<GEMM_GRID, 128>>>(zc, 128, 128, 256,
                                    W1_r + (size_t)HH * HH, b1_r + HH,
                                    W2_r + (size_t)HH * HH, b2_r + HH);
    bn_apply_kernel<<<bn_grid, 256>>>(zc, 128, -1, 256, batch, pool, bn_gr + HH, bn_br + HH);

    (void)in_sizes; (void)n_in; (void)out_size;
}